// round 1
// baseline (speedup 1.0000x reference)
#include <cuda_runtime.h>
#include <math.h>

#define B    8
#define NTOK 2048
#define FIN  256
#define D    128
#define ALPHA 0.2f
#define CHUNK  128
#define NCHUNK (NTOK/CHUNK)   // 16

// ---------------- scratch (__device__ globals; no allocation allowed) --------
__device__ float d_Wh[B*NTOK*D];          // 8.4 MB
__device__ float d_s1[B*NTOK];
__device__ float d_s2[B*NTOK];
__device__ float d_s2s[B*NTOK];           // sorted s2
__device__ int   d_perm[B*NTOK];          // sort permutation of s2
__device__ float d_g1[B*NTOK];            // exp(s2)/Z      (sorted order)
__device__ float d_g2[B*NTOK];            // exp(a*s2)/Z    (sorted order)
__device__ float d_loc1[B*NTOK*D];        // chunk-local inclusive prefix of g1*Wh
__device__ float d_loc2[B*NTOK*D];        // chunk-local inclusive prefix of g2*Wh
__device__ float d_off1[B*NCHUNK*D];      // exclusive chunk offsets
__device__ float d_off2[B*NCHUNK*D];
__device__ float d_tot1[B*D];
__device__ float d_tot2[B*D];

// ---------------- K1: Wh = h @ W, fused s1 = Wh@a1, s2 = Wh@a2 ---------------
__global__ void __launch_bounds__(256) k_gemm(const float* __restrict__ h,
                                              const float* __restrict__ W,
                                              const float* __restrict__ a)
{
    __shared__ float As[64][32];
    __shared__ float Bs[32][128];
    __shared__ float a1s[128], a2s[128];

    const int tid = threadIdx.x;
    const int rowBase = blockIdx.x * 64;        // global row in [0, B*NTOK)
    if (tid < 128) { a1s[tid] = a[tid]; a2s[tid] = a[128 + tid]; }

    const int cg = tid & 31;     // col group: 4 cols each
    const int rg = tid >> 5;     // row group: 8 rows each  (warp == one rg)

    float acc[8][4] = {};

    for (int kt = 0; kt < FIN; kt += 32) {
        #pragma unroll
        for (int l = 0; l < 2; l++) {                  // A tile: 64x32
            int f4 = tid * 2 + l;                      // 0..511 float4s
            int r  = f4 >> 3;
            int c4 = f4 & 7;
            float4 v = *(const float4*)&h[(size_t)(rowBase + r) * FIN + kt + c4 * 4];
            *(float4*)&As[r][c4 * 4] = v;
        }
        #pragma unroll
        for (int l = 0; l < 4; l++) {                  // B tile: 32x128
            int f4 = tid * 4 + l;                      // 0..1023
            int r  = f4 >> 5;
            int c4 = f4 & 31;
            float4 v = *(const float4*)&W[(size_t)(kt + r) * D + c4 * 4];
            *(float4*)&Bs[r][c4 * 4] = v;
        }
        __syncthreads();
        #pragma unroll
        for (int kk = 0; kk < 32; kk++) {
            float bf[4];
            *(float4*)bf = *(float4*)&Bs[kk][cg * 4];
            #pragma unroll
            for (int m = 0; m < 8; m++) {
                float av = As[rg * 8 + m][kk];         // warp-broadcast
                #pragma unroll
                for (int n = 0; n < 4; n++) acc[m][n] += av * bf[n];
            }
        }
        __syncthreads();
    }

    #pragma unroll
    for (int m = 0; m < 8; m++) {
        int row = rowBase + rg * 8 + m;
        *(float4*)&d_Wh[(size_t)row * D + cg * 4] = *(float4*)acc[m];
        float p1 = 0.f, p2 = 0.f;
        #pragma unroll
        for (int n = 0; n < 4; n++) {
            p1 += acc[m][n] * a1s[cg * 4 + n];
            p2 += acc[m][n] * a2s[cg * 4 + n];
        }
        #pragma unroll
        for (int o = 16; o > 0; o >>= 1) {
            p1 += __shfl_xor_sync(0xffffffffu, p1, o);
            p2 += __shfl_xor_sync(0xffffffffu, p2, o);
        }
        if (cg == 0) { d_s1[row] = p1; d_s2[row] = p2; }
    }
}

// ------- K2: per batch — sort s1 & s2, scalar scans, Z[j], g1/g2 -------------
__global__ void __launch_bounds__(1024) k_prep()
{
    __shared__ float ss1[NTOK];
    __shared__ float pe[NTOK];      // inclusive prefix of exp(s1_sorted)
    __shared__ float pa[NTOK];      // inclusive prefix of exp(a*s1_sorted)
    __shared__ float ss2[NTOK];
    __shared__ int   ix2[NTOK];

    const int b = blockIdx.x, tid = threadIdx.x;
    const float* s1 = d_s1 + b * NTOK;
    const float* s2 = d_s2 + b * NTOK;

    ss1[tid] = s1[tid];  ss1[tid + 1024] = s1[tid + 1024];
    ss2[tid] = s2[tid];  ss2[tid + 1024] = s2[tid + 1024];
    ix2[tid] = tid;      ix2[tid + 1024] = tid + 1024;
    __syncthreads();

    // bitonic sort: keys ss1, and (ss2, ix2) pairs, simultaneously
    for (int k = 2; k <= NTOK; k <<= 1) {
        for (int j = k >> 1; j > 0; j >>= 1) {
            #pragma unroll
            for (int t = 0; t < 2; t++) {
                int i   = tid + t * 1024;
                int ixj = i ^ j;
                if (ixj > i) {
                    bool up = ((i & k) == 0);
                    float A = ss1[i], Bv = ss1[ixj];
                    if ((A > Bv) == up) { ss1[i] = Bv; ss1[ixj] = A; }
                    float C = ss2[i], Dv = ss2[ixj];
                    if ((C > Dv) == up) {
                        ss2[i] = Dv; ss2[ixj] = C;
                        int tp = ix2[i]; ix2[i] = ix2[ixj]; ix2[ixj] = tp;
                    }
                }
            }
            __syncthreads();
        }
    }

    pe[tid]        = expf(ss1[tid]);
    pe[tid + 1024] = expf(ss1[tid + 1024]);
    pa[tid]        = expf(ALPHA * ss1[tid]);
    pa[tid + 1024] = expf(ALPHA * ss1[tid + 1024]);
    __syncthreads();

    for (int off = 1; off < NTOK; off <<= 1) {          // Hillis-Steele scan
        float v0e = pe[tid] + (tid >= off ? pe[tid - off] : 0.f);
        float v0a = pa[tid] + (tid >= off ? pa[tid - off] : 0.f);
        int i1 = tid + 1024;                             // i1 >= off always
        float v1e = pe[i1] + pe[i1 - off];
        float v1a = pa[i1] + pa[i1 - off];
        __syncthreads();
        pe[tid] = v0e; pa[tid] = v0a; pe[i1] = v1e; pa[i1] = v1a;
        __syncthreads();
    }

    const float totE = pe[NTOK - 1], totA = pa[NTOK - 1];

    #pragma unroll
    for (int t = 0; t < 2; t++) {
        int kk = tid + t * 1024;
        float s2v = ss2[kk];
        float key = -s2v;
        int lo = 0, hi = NTOK;
        while (lo < hi) { int mid = (lo + hi) >> 1; if (ss1[mid] < key) lo = mid + 1; else hi = mid; }
        // indices >= lo: s1 >= -s2  -> e >= 0 branch
        float preE = lo > 0 ? pe[lo - 1] : 0.f;
        float preA = lo > 0 ? pa[lo - 1] : 0.f;
        float e2  = expf(s2v);
        float ea2 = expf(ALPHA * s2v);
        float Z   = e2 * (totE - preE) + ea2 * preA;
        float inv = 1.f / Z;
        d_g1[b * NTOK + kk]  = e2  * inv;
        d_g2[b * NTOK + kk]  = ea2 * inv;
        d_s2s[b * NTOK + kk] = s2v;
        d_perm[b * NTOK + kk] = ix2[kk];
    }
}

// ------- K3: chunk-local inclusive prefix sums of g1*Wh, g2*Wh (double acc) --
__global__ void __launch_bounds__(128) k_scan()
{
    const int b = blockIdx.y, c = blockIdx.x, d = threadIdx.x;
    const int base = b * NTOK + c * CHUNK;
    double a1 = 0.0, a2 = 0.0;
    for (int r = 0; r < CHUNK; r++) {
        int k = base + r;
        int j = d_perm[k];
        float w  = d_Wh[((size_t)b * NTOK + j) * D + d];
        a1 += (double)d_g1[k] * (double)w;
        a2 += (double)d_g2[k] * (double)w;
        d_loc1[(size_t)k * D + d] = (float)a1;
        d_loc2[(size_t)k * D + d] = (float)a2;
    }
}

// ------- K4: scan chunk totals -> exclusive offsets + totals ------------------
__global__ void __launch_bounds__(128) k_off()
{
    const int b = blockIdx.x, d = threadIdx.x;
    double r1 = 0.0, r2 = 0.0;
    for (int c = 0; c < NCHUNK; c++) {
        d_off1[(b * NCHUNK + c) * D + d] = (float)r1;
        d_off2[(b * NCHUNK + c) * D + d] = (float)r2;
        r1 += d_loc1[((size_t)b * NTOK + c * CHUNK + CHUNK - 1) * D + d];
        r2 += d_loc2[((size_t)b * NTOK + c * CHUNK + CHUNK - 1) * D + d];
    }
    d_tot1[b * D + d] = (float)r1;
    d_tot2[b * D + d] = (float)r2;
}

// ------- K5: per-query combine + ELU -----------------------------------------
__global__ void __launch_bounds__(128) k_out(float* __restrict__ out)
{
    __shared__ float ss2[NTOK];
    __shared__ int   tarr[16];
    __shared__ float e1v[16], e2v[16];

    const int b = blockIdx.y;
    const int rowBase = blockIdx.x * 16;
    const int d = threadIdx.x;

    #pragma unroll
    for (int l = 0; l < NTOK / 128; l++)
        ss2[l * 128 + d] = d_s2s[b * NTOK + l * 128 + d];
    __syncthreads();

    if (d < 16) {
        float s1 = d_s1[b * NTOK + rowBase + d];
        float key = -s1;
        int lo = 0, hi = NTOK;
        while (lo < hi) { int mid = (lo + hi) >> 1; if (ss2[mid] < key) lo = mid + 1; else hi = mid; }
        tarr[d] = lo;                 // indices >= lo: s2 >= -s1 -> e >= 0 branch
        e1v[d] = expf(s1);
        e2v[d] = expf(ALPHA * s1);
    }
    __syncthreads();

    const float tot1 = d_tot1[b * D + d];

    #pragma unroll 4
    for (int r = 0; r < 16; r++) {
        int t = tarr[r];
        float P1 = 0.f, P2 = 0.f;
        if (t > 0) {
            int k = t - 1;
            int c = k >> 7;
            P1 = d_loc1[((size_t)b * NTOK + k) * D + d] + d_off1[(b * NCHUNK + c) * D + d];
            P2 = d_loc2[((size_t)b * NTOK + k) * D + d] + d_off2[(b * NCHUNK + c) * D + d];
        }
        float val = e1v[r] * (tot1 - P1) + e2v[r] * P2;
        out[((size_t)b * NTOK + rowBase + r) * D + d] = val > 0.f ? val : expm1f(val);
    }
}

// -----------------------------------------------------------------------------
extern "C" void kernel_launch(void* const* d_in, const int* in_sizes, int n_in,
                              void* d_out, int out_size)
{
    const float* h = (const float*)d_in[0];   // [8,2048,256]
    const float* W = (const float*)d_in[1];   // [256,128]
    const float* a = (const float*)d_in[2];   // [256,1]
    float* out = (float*)d_out;               // [8,2048,128]

    k_gemm<<<(B * NTOK) / 64, 256>>>(h, W, a);
    k_prep<<<B, 1024>>>();
    k_scan<<<dim3(NCHUNK, B), 128>>>();
    k_off<<<B, 128>>>();
    k_out<<<dim3(NTOK / 16, B), 128>>>(out);
}

// round 2
// speedup vs baseline: 1.3630x; 1.3630x over previous
#include <cuda_runtime.h>
#include <math.h>

#define B    8
#define NTOK 2048
#define FIN  256
#define D    128
#define ALPHA 0.2f
#define CHUNK  64
#define NCHUNK (NTOK/CHUNK)   // 32
#define QPB    64             // queries per k_out block

// ---------------- scratch (__device__ globals; no allocation allowed) --------
__device__ float d_Wh[B*NTOK*D];
__device__ float d_s1[B*NTOK];
__device__ float d_s2[B*NTOK];
__device__ float d_s2s[B*NTOK];           // sorted s2
__device__ int   d_perm[B*NTOK];          // sort permutation of s2
__device__ float d_g1[B*NTOK];            // exp(s2)/Z      (sorted order)
__device__ float d_g2[B*NTOK];            // exp(a*s2)/Z    (sorted order)
__device__ float d_loc1[B*NTOK*D];        // chunk-local inclusive prefix of g1*Wh
__device__ float d_loc2[B*NTOK*D];        // chunk-local inclusive prefix of g2*Wh
__device__ float d_ct1[B*NCHUNK*D];       // per-chunk totals
__device__ float d_ct2[B*NCHUNK*D];

// ---------------- K1: Wh = h @ W (128x128 tile, 8x8/thread), fused s1/s2 -----
__global__ void __launch_bounds__(256) k_gemm(const float* __restrict__ h,
                                              const float* __restrict__ W,
                                              const float* __restrict__ a)
{
    __shared__ float As[128][36];     // row-major, padded (+4) for conflict-free
    __shared__ float Bs[32][128];     // k-major
    __shared__ float a1s[128], a2s[128];

    const int tid = threadIdx.x;
    const int rowBase = blockIdx.x * 128;
    if (tid < 128) { a1s[tid] = a[tid]; a2s[tid] = a[128 + tid]; }

    const int tx = tid & 15;          // col group
    const int ty = tid >> 4;          // row group

    float acc[8][8] = {};

    for (int kt = 0; kt < FIN; kt += 32) {
        #pragma unroll
        for (int l = 0; l < 4; l++) {                  // A tile: 128 rows x 32 k
            int f4 = tid + l * 256;                    // 0..1023 float4s
            int r  = f4 >> 3;
            int c4 = f4 & 7;
            float4 v = *(const float4*)&h[(size_t)(rowBase + r) * FIN + kt + c4 * 4];
            *(float4*)&As[r][c4 * 4] = v;
        }
        #pragma unroll
        for (int l = 0; l < 4; l++) {                  // B tile: 32 k x 128 cols
            int f4 = tid + l * 256;
            int r  = f4 >> 5;
            int c4 = f4 & 31;
            *(float4*)&Bs[r][c4 * 4] = *(const float4*)&W[(size_t)(kt + r) * D + c4 * 4];
        }
        __syncthreads();
        #pragma unroll
        for (int kk = 0; kk < 32; kk++) {
            float av[8], bv[8];
            #pragma unroll
            for (int i = 0; i < 4; i++) {
                av[i]     = As[ty * 4 + i][kk];
                av[i + 4] = As[ty * 4 + 64 + i][kk];
            }
            *(float4*)&bv[0] = *(float4*)&Bs[kk][tx * 4];
            *(float4*)&bv[4] = *(float4*)&Bs[kk][tx * 4 + 64];
            #pragma unroll
            for (int i = 0; i < 8; i++)
                #pragma unroll
                for (int j = 0; j < 8; j++) acc[i][j] += av[i] * bv[j];
        }
        __syncthreads();
    }

    float a1v[8], a2v[8];
    #pragma unroll
    for (int j = 0; j < 8; j++) {
        int col = tx * 4 + (j < 4 ? j : 60 + j);
        a1v[j] = a1s[col];
        a2v[j] = a2s[col];
    }

    #pragma unroll
    for (int i = 0; i < 8; i++) {
        int row = rowBase + ty * 4 + (i < 4 ? i : 60 + i);
        *(float4*)&d_Wh[(size_t)row * D + tx * 4]      = *(float4*)&acc[i][0];
        *(float4*)&d_Wh[(size_t)row * D + tx * 4 + 64] = *(float4*)&acc[i][4];
        float p1 = 0.f, p2 = 0.f;
        #pragma unroll
        for (int j = 0; j < 8; j++) {
            p1 += acc[i][j] * a1v[j];
            p2 += acc[i][j] * a2v[j];
        }
        #pragma unroll
        for (int o = 8; o > 0; o >>= 1) {             // reduce across the 16 tx lanes
            p1 += __shfl_xor_sync(0xffffffffu, p1, o);
            p2 += __shfl_xor_sync(0xffffffffu, p2, o);
        }
        if (tx == 0) { d_s1[row] = p1; d_s2[row] = p2; }
    }
}

// ------- K2: per batch — sort s1 & s2, scalar scans, Z[j], g1/g2 -------------
__global__ void __launch_bounds__(1024) k_prep()
{
    __shared__ float ss1[NTOK];
    __shared__ float pe[NTOK];
    __shared__ float pa[NTOK];
    __shared__ float ss2[NTOK];
    __shared__ int   ix2[NTOK];

    const int b = blockIdx.x, tid = threadIdx.x;
    const float* s1 = d_s1 + b * NTOK;
    const float* s2 = d_s2 + b * NTOK;

    ss1[tid] = s1[tid];  ss1[tid + 1024] = s1[tid + 1024];
    ss2[tid] = s2[tid];  ss2[tid + 1024] = s2[tid + 1024];
    ix2[tid] = tid;      ix2[tid + 1024] = tid + 1024;
    __syncthreads();

    for (int k = 2; k <= NTOK; k <<= 1) {
        for (int j = k >> 1; j > 0; j >>= 1) {
            #pragma unroll
            for (int t = 0; t < 2; t++) {
                int i   = tid + t * 1024;
                int ixj = i ^ j;
                if (ixj > i) {
                    bool up = ((i & k) == 0);
                    float A = ss1[i], Bv = ss1[ixj];
                    if ((A > Bv) == up) { ss1[i] = Bv; ss1[ixj] = A; }
                    float C = ss2[i], Dv = ss2[ixj];
                    if ((C > Dv) == up) {
                        ss2[i] = Dv; ss2[ixj] = C;
                        int tp = ix2[i]; ix2[i] = ix2[ixj]; ix2[ixj] = tp;
                    }
                }
            }
            __syncthreads();
        }
    }

    pe[tid]        = expf(ss1[tid]);
    pe[tid + 1024] = expf(ss1[tid + 1024]);
    pa[tid]        = expf(ALPHA * ss1[tid]);
    pa[tid + 1024] = expf(ALPHA * ss1[tid + 1024]);
    __syncthreads();

    for (int off = 1; off < NTOK; off <<= 1) {
        float v0e = pe[tid] + (tid >= off ? pe[tid - off] : 0.f);
        float v0a = pa[tid] + (tid >= off ? pa[tid - off] : 0.f);
        int i1 = tid + 1024;
        float v1e = pe[i1] + pe[i1 - off];
        float v1a = pa[i1] + pa[i1 - off];
        __syncthreads();
        pe[tid] = v0e; pa[tid] = v0a; pe[i1] = v1e; pa[i1] = v1a;
        __syncthreads();
    }

    const float totE = pe[NTOK - 1], totA = pa[NTOK - 1];

    #pragma unroll
    for (int t = 0; t < 2; t++) {
        int kk = tid + t * 1024;
        float s2v = ss2[kk];
        float key = -s2v;
        int lo = 0, hi = NTOK;
        while (lo < hi) { int mid = (lo + hi) >> 1; if (ss1[mid] < key) lo = mid + 1; else hi = mid; }
        float preE = lo > 0 ? pe[lo - 1] : 0.f;
        float preA = lo > 0 ? pa[lo - 1] : 0.f;
        float e2  = expf(s2v);
        float ea2 = expf(ALPHA * s2v);
        float Z   = e2 * (totE - preE) + ea2 * preA;
        float inv = 1.f / Z;
        d_g1[b * NTOK + kk]  = e2  * inv;
        d_g2[b * NTOK + kk]  = ea2 * inv;
        d_s2s[b * NTOK + kk] = s2v;
        d_perm[b * NTOK + kk] = ix2[kk];
    }
}

// ------- K3: chunk-local Kahan prefix sums of g1*Wh, g2*Wh --------------------
__global__ void __launch_bounds__(128) k_scan()
{
    const int b = blockIdx.y, c = blockIdx.x, d = threadIdx.x;
    const int base = b * NTOK + c * CHUNK;
    float s1a = 0.f, c1a = 0.f, s2a = 0.f, c2a = 0.f;
    #pragma unroll 4
    for (int r = 0; r < CHUNK; r++) {
        int k = base + r;
        int j = d_perm[k];
        float w  = d_Wh[((size_t)b * NTOK + j) * D + d];
        float t1 = d_g1[k] * w;
        float t2 = d_g2[k] * w;
        float y1 = t1 - c1a; float u1 = s1a + y1; c1a = (u1 - s1a) - y1; s1a = u1;
        float y2 = t2 - c2a; float u2 = s2a + y2; c2a = (u2 - s2a) - y2; s2a = u2;
        d_loc1[(size_t)k * D + d] = s1a;
        d_loc2[(size_t)k * D + d] = s2a;
    }
    d_ct1[(b * NCHUNK + c) * D + d] = s1a;
    d_ct2[(b * NCHUNK + c) * D + d] = s2a;
}

// ------- K4: per-query combine + ELU (chunk offsets computed in-block) --------
__global__ void __launch_bounds__(128) k_out(float* __restrict__ out)
{
    __shared__ float ss2[NTOK];
    __shared__ float cp1[NCHUNK][D];
    __shared__ float cp2[NCHUNK][D];
    __shared__ int   tarr[QPB];
    __shared__ float e1v[QPB], e2v[QPB];

    const int b = blockIdx.y;
    const int rowBase = blockIdx.x * QPB;
    const int d = threadIdx.x;

    #pragma unroll
    for (int l = 0; l < NTOK / 128; l++)
        ss2[l * 128 + d] = d_s2s[b * NTOK + l * 128 + d];

    // exclusive prefix of chunk totals (per output dim d)
    float run1 = 0.f, run2 = 0.f;
    #pragma unroll
    for (int cc = 0; cc < NCHUNK; cc++) {
        cp1[cc][d] = run1;
        cp2[cc][d] = run2;
        run1 += d_ct1[(b * NCHUNK + cc) * D + d];
        run2 += d_ct2[(b * NCHUNK + cc) * D + d];
    }
    const float tot1 = run1;
    __syncthreads();

    if (d < QPB) {
        float s1 = d_s1[b * NTOK + rowBase + d];
        float key = -s1;
        int lo = 0, hi = NTOK;
        while (lo < hi) { int mid = (lo + hi) >> 1; if (ss2[mid] < key) lo = mid + 1; else hi = mid; }
        tarr[d] = lo;                 // indices >= lo: s2 >= -s1 -> e >= 0 branch
        e1v[d] = expf(s1);
        e2v[d] = expf(ALPHA * s1);
    }
    __syncthreads();

    #pragma unroll 4
    for (int r = 0; r < QPB; r++) {
        int t = tarr[r];
        float P1 = 0.f, P2 = 0.f;
        if (t > 0) {
            int k = t - 1;
            int c = k / CHUNK;
            P1 = d_loc1[((size_t)b * NTOK + k) * D + d] + cp1[c][d];
            P2 = d_loc2[((size_t)b * NTOK + k) * D + d] + cp2[c][d];
        }
        float val = e1v[r] * (tot1 - P1) + e2v[r] * P2;
        out[((size_t)b * NTOK + rowBase + r) * D + d] = val > 0.f ? val : expm1f(val);
    }
}

// -----------------------------------------------------------------------------
extern "C" void kernel_launch(void* const* d_in, const int* in_sizes, int n_in,
                              void* d_out, int out_size)
{
    const float* h = (const float*)d_in[0];   // [8,2048,256]
    const float* W = (const float*)d_in[1];   // [256,128]
    const float* a = (const float*)d_in[2];   // [256,1]
    float* out = (float*)d_out;               // [8,2048,128]

    k_gemm<<<(B * NTOK) / 128, 256>>>(h, W, a);
    k_prep<<<B, 1024>>>();
    k_scan<<<dim3(NCHUNK, B), 128>>>();
    k_out<<<dim3(NTOK / QPB, B), 128>>>(out);
}

// round 3
// speedup vs baseline: 1.9239x; 1.4116x over previous
#include <cuda_runtime.h>
#include <math.h>

#define B    8
#define NTOK 2048
#define FIN  256
#define D    128
#define ALPHA 0.2f
#define CHUNK  32
#define NCHUNK (NTOK/CHUNK)   // 64

// ---------------- scratch (__device__ globals) --------------------------------
__device__ float d_Wh[B*NTOK*D];
__device__ float d_s1[B*NTOK];
__device__ float d_s2[B*NTOK];
__device__ float d_ss1[B*NTOK];           // sorted s1
__device__ float d_pe[B*NTOK];            // inclusive prefix of exp(ss1)
__device__ float d_pa[B*NTOK];            // inclusive prefix of exp(a*ss1)
__device__ float d_s2s[B*NTOK];           // sorted s2
__device__ int   d_perm[B*NTOK];          // sort permutation of s2
__device__ float d_g1[B*NTOK];            // exp(s2)/Z      (sorted order)
__device__ float d_g2[B*NTOK];            // exp(a*s2)/Z    (sorted order)
__device__ int   d_tq[B*NTOK];            // per-query threshold index
__device__ float d_e1[B*NTOK];            // exp(s1_i)
__device__ float d_e2[B*NTOK];            // exp(a*s1_i)
__device__ float d_loc1[B*NTOK*D];        // chunk-local inclusive prefix of g1*Wh
__device__ float d_loc2[B*NTOK*D];        // chunk-local inclusive prefix of g2*Wh
__device__ float d_ct1[B*NCHUNK*D];       // per-chunk totals
__device__ float d_ct2[B*NCHUNK*D];
__device__ float d_cp1[B*NCHUNK*D];       // exclusive chunk offsets
__device__ float d_cp2[B*NCHUNK*D];
__device__ float d_tot1[B*D];

// ---------------- K1: Wh = h @ W (128x128 tile, 8x8/thread), fused s1/s2 -----
__global__ void __launch_bounds__(256) k_gemm(const float* __restrict__ h,
                                              const float* __restrict__ W,
                                              const float* __restrict__ a)
{
    __shared__ float As[128][36];
    __shared__ float Bs[32][128];
    __shared__ float a1s[128], a2s[128];

    const int tid = threadIdx.x;
    const int rowBase = blockIdx.x * 128;
    if (tid < 128) { a1s[tid] = a[tid]; a2s[tid] = a[128 + tid]; }

    const int tx = tid & 15;
    const int ty = tid >> 4;

    float acc[8][8] = {};

    for (int kt = 0; kt < FIN; kt += 32) {
        #pragma unroll
        for (int l = 0; l < 4; l++) {
            int f4 = tid + l * 256;
            int r  = f4 >> 3;
            int c4 = f4 & 7;
            float4 v = *(const float4*)&h[(size_t)(rowBase + r) * FIN + kt + c4 * 4];
            *(float4*)&As[r][c4 * 4] = v;
        }
        #pragma unroll
        for (int l = 0; l < 4; l++) {
            int f4 = tid + l * 256;
            int r  = f4 >> 5;
            int c4 = f4 & 31;
            *(float4*)&Bs[r][c4 * 4] = *(const float4*)&W[(size_t)(kt + r) * D + c4 * 4];
        }
        __syncthreads();
        #pragma unroll
        for (int kk = 0; kk < 32; kk++) {
            float av[8], bv[8];
            #pragma unroll
            for (int i = 0; i < 4; i++) {
                av[i]     = As[ty * 4 + i][kk];
                av[i + 4] = As[ty * 4 + 64 + i][kk];
            }
            *(float4*)&bv[0] = *(float4*)&Bs[kk][tx * 4];
            *(float4*)&bv[4] = *(float4*)&Bs[kk][tx * 4 + 64];
            #pragma unroll
            for (int i = 0; i < 8; i++)
                #pragma unroll
                for (int j = 0; j < 8; j++) acc[i][j] += av[i] * bv[j];
        }
        __syncthreads();
    }

    float a1v[8], a2v[8];
    #pragma unroll
    for (int j = 0; j < 8; j++) {
        int col = tx * 4 + (j < 4 ? j : 60 + j);
        a1v[j] = a1s[col];
        a2v[j] = a2s[col];
    }

    #pragma unroll
    for (int i = 0; i < 8; i++) {
        int row = rowBase + ty * 4 + (i < 4 ? i : 60 + i);
        *(float4*)&d_Wh[(size_t)row * D + tx * 4]      = *(float4*)&acc[i][0];
        *(float4*)&d_Wh[(size_t)row * D + tx * 4 + 64] = *(float4*)&acc[i][4];
        float p1 = 0.f, p2 = 0.f;
        #pragma unroll
        for (int j = 0; j < 8; j++) {
            p1 += acc[i][j] * a1v[j];
            p2 += acc[i][j] * a2v[j];
        }
        #pragma unroll
        for (int o = 8; o > 0; o >>= 1) {
            p1 += __shfl_xor_sync(0xffffffffu, p1, o);
            p2 += __shfl_xor_sync(0xffffffffu, p2, o);
        }
        if (tx == 0) { d_s1[row] = p1; d_s2[row] = p2; }
    }
}

// ------- K2a: bitonic sort. role 0: s1 -> ss1 + exp-prefix scans.  -----------
// -------       role 1: s2 -> s2s + perm.                            ----------
__global__ void __launch_bounds__(1024) k_sort()
{
    __shared__ float key[NTOK];
    __shared__ int   idx[NTOK];
    __shared__ float pe[NTOK];
    __shared__ float pa[NTOK];

    const int role = blockIdx.x, b = blockIdx.y, tid = threadIdx.x;
    const float* src = (role == 0 ? d_s1 : d_s2) + b * NTOK;

    key[tid] = src[tid];  key[tid + 1024] = src[tid + 1024];
    idx[tid] = tid;       idx[tid + 1024] = tid + 1024;
    __syncthreads();

    for (int k = 2; k <= NTOK; k <<= 1) {
        for (int j = k >> 1; j > 0; j >>= 1) {
            #pragma unroll
            for (int t = 0; t < 2; t++) {
                int i   = tid + t * 1024;
                int ixj = i ^ j;
                if (ixj > i) {
                    bool up = ((i & k) == 0);
                    float A = key[i], Bv = key[ixj];
                    if ((A > Bv) == up) {
                        key[i] = Bv; key[ixj] = A;
                        int tp = idx[i]; idx[i] = idx[ixj]; idx[ixj] = tp;
                    }
                }
            }
            __syncthreads();
        }
    }

    if (role == 1) {
        d_s2s[b * NTOK + tid]         = key[tid];
        d_s2s[b * NTOK + tid + 1024]  = key[tid + 1024];
        d_perm[b * NTOK + tid]        = idx[tid];
        d_perm[b * NTOK + tid + 1024] = idx[tid + 1024];
        return;
    }

    pe[tid]        = expf(key[tid]);
    pe[tid + 1024] = expf(key[tid + 1024]);
    pa[tid]        = expf(ALPHA * key[tid]);
    pa[tid + 1024] = expf(ALPHA * key[tid + 1024]);
    __syncthreads();

    for (int off = 1; off < NTOK; off <<= 1) {
        float v0e = pe[tid] + (tid >= off ? pe[tid - off] : 0.f);
        float v0a = pa[tid] + (tid >= off ? pa[tid - off] : 0.f);
        int i1 = tid + 1024;
        float v1e = pe[i1] + pe[i1 - off];
        float v1a = pa[i1] + pa[i1 - off];
        __syncthreads();
        pe[tid] = v0e; pa[tid] = v0a; pe[i1] = v1e; pa[i1] = v1a;
        __syncthreads();
    }

    d_ss1[b * NTOK + tid]        = key[tid];
    d_ss1[b * NTOK + tid + 1024] = key[tid + 1024];
    d_pe[b * NTOK + tid]         = pe[tid];
    d_pe[b * NTOK + tid + 1024]  = pe[tid + 1024];
    d_pa[b * NTOK + tid]         = pa[tid];
    d_pa[b * NTOK + tid + 1024]  = pa[tid + 1024];
}

// ------- K2b: per-j g1/g2 (Z via sorted-s1 scans) + per-i threshold/exps -----
__global__ void __launch_bounds__(256) k_gfill()
{
    __shared__ float ss1[NTOK];
    __shared__ float ss2[NTOK];

    const int b = blockIdx.y, tid = threadIdx.x;
    const int base = blockIdx.x * 256;

    #pragma unroll
    for (int l = 0; l < 2; l++) {
        int f4 = tid + l * 256;                    // 0..511 float4s
        *(float4*)&ss1[f4 * 4] = *(const float4*)&d_ss1[b * NTOK + f4 * 4];
        *(float4*)&ss2[f4 * 4] = *(const float4*)&d_s2s[b * NTOK + f4 * 4];
    }
    __syncthreads();

    const float totE = d_pe[b * NTOK + NTOK - 1];

    // j-side: g1/g2 at sorted position jj
    {
        int jj = base + tid;
        float s2v = ss2[jj];
        float keyv = -s2v;
        int lo = 0, hi = NTOK;
        while (lo < hi) { int mid = (lo + hi) >> 1; if (ss1[mid] < keyv) lo = mid + 1; else hi = mid; }
        float preE = lo > 0 ? d_pe[b * NTOK + lo - 1] : 0.f;
        float preA = lo > 0 ? d_pa[b * NTOK + lo - 1] : 0.f;
        float e2  = expf(s2v);
        float ea2 = expf(ALPHA * s2v);
        float inv = 1.f / (e2 * (totE - preE) + ea2 * preA);
        d_g1[b * NTOK + jj] = e2  * inv;
        d_g2[b * NTOK + jj] = ea2 * inv;
    }

    // i-side: threshold + exps at original query index i
    {
        int i = base + tid;
        float s1v = d_s1[b * NTOK + i];
        float keyv = -s1v;
        int lo = 0, hi = NTOK;
        while (lo < hi) { int mid = (lo + hi) >> 1; if (ss2[mid] < keyv) lo = mid + 1; else hi = mid; }
        d_tq[b * NTOK + i] = lo;
        d_e1[b * NTOK + i] = expf(s1v);
        d_e2[b * NTOK + i] = expf(ALPHA * s1v);
    }
}

// ------- K3: chunk-local Kahan prefix sums of g1*Wh, g2*Wh --------------------
__global__ void __launch_bounds__(128) k_scan()
{
    __shared__ int   sp[CHUNK];
    __shared__ float sg1[CHUNK], sg2[CHUNK];

    const int b = blockIdx.y, c = blockIdx.x, d = threadIdx.x;
    const int base = b * NTOK + c * CHUNK;

    if (d < CHUNK)                 sp [d]      = d_perm[base + d];
    else if (d < 2 * CHUNK)        sg1[d - CHUNK]     = d_g1[base + d - CHUNK];
    else if (d < 3 * CHUNK)        sg2[d - 2 * CHUNK] = d_g2[base + d - 2 * CHUNK];
    __syncthreads();

    float s1a = 0.f, c1a = 0.f, s2a = 0.f, c2a = 0.f;
    #pragma unroll
    for (int r = 0; r < CHUNK; r++) {
        float w  = d_Wh[((size_t)b * NTOK + sp[r]) * D + d];
        float t1 = sg1[r] * w;
        float t2 = sg2[r] * w;
        float y1 = t1 - c1a; float u1 = s1a + y1; c1a = (u1 - s1a) - y1; s1a = u1;
        float y2 = t2 - c2a; float u2 = s2a + y2; c2a = (u2 - s2a) - y2; s2a = u2;
        d_loc1[(size_t)(base + r) * D + d] = s1a;
        d_loc2[(size_t)(base + r) * D + d] = s2a;
    }
    d_ct1[(b * NCHUNK + c) * D + d] = s1a;
    d_ct2[(b * NCHUNK + c) * D + d] = s2a;
}

// ------- K4: two-phase exclusive scan of chunk totals -------------------------
__global__ void __launch_bounds__(1024) k_coff()
{
    __shared__ float part1[8][D];
    __shared__ float part2[8][D];

    const int b = blockIdx.x;
    const int d = threadIdx.x & 127;
    const int g = threadIdx.x >> 7;            // 8 groups x 8 chunks

    float v1[8], v2[8];
    #pragma unroll
    for (int r = 0; r < 8; r++) {
        int c = g * 8 + r;
        v1[r] = d_ct1[(b * NCHUNK + c) * D + d];
        v2[r] = d_ct2[(b * NCHUNK + c) * D + d];
    }
    float run1 = 0.f, run2 = 0.f;
    #pragma unroll
    for (int r = 0; r < 8; r++) {
        float t1 = v1[r]; v1[r] = run1; run1 += t1;
        float t2 = v2[r]; v2[r] = run2; run2 += t2;
    }
    part1[g][d] = run1;
    part2[g][d] = run2;
    __syncthreads();

    if (g == 0) {
        float r1 = 0.f, r2 = 0.f;
        #pragma unroll
        for (int gg = 0; gg < 8; gg++) {
            float t1 = part1[gg][d]; part1[gg][d] = r1; r1 += t1;
            float t2 = part2[gg][d]; part2[gg][d] = r2; r2 += t2;
        }
        d_tot1[b * D + d] = r1;
    }
    __syncthreads();

    const float o1 = part1[g][d];
    const float o2 = part2[g][d];
    #pragma unroll
    for (int r = 0; r < 8; r++) {
        int c = g * 8 + r;
        d_cp1[(b * NCHUNK + c) * D + d] = o1 + v1[r];
        d_cp2[(b * NCHUNK + c) * D + d] = o2 + v2[r];
    }
}

// ------- K5: wide gather + ELU  (8 queries/block, float4/thread) --------------
__global__ void __launch_bounds__(256) k_out(float* __restrict__ out)
{
    const int gq   = blockIdx.x * 8 + (threadIdx.x >> 5);   // global query row
    const int lane = threadIdx.x & 31;
    const int b    = gq >> 11;                               // / NTOK
    const int d4   = lane * 4;

    const int   t  = d_tq[gq];
    const float e1 = d_e1[gq];
    const float e2 = d_e2[gq];

    float4 tot = *(const float4*)&d_tot1[b * D + d4];
    float4 P1 = {0.f, 0.f, 0.f, 0.f};
    float4 P2 = {0.f, 0.f, 0.f, 0.f};

    if (t > 0) {
        int k = t - 1;
        int c = k >> 5;                                      // / CHUNK
        size_t kb = (size_t)(b * NTOK + k) * D + d4;
        size_t cb = (size_t)(b * NCHUNK + c) * D + d4;
        float4 l1 = *(const float4*)&d_loc1[kb];
        float4 l2 = *(const float4*)&d_loc2[kb];
        float4 c1 = *(const float4*)&d_cp1[cb];
        float4 c2 = *(const float4*)&d_cp2[cb];
        P1.x = l1.x + c1.x; P1.y = l1.y + c1.y; P1.z = l1.z + c1.z; P1.w = l1.w + c1.w;
        P2.x = l2.x + c2.x; P2.y = l2.y + c2.y; P2.z = l2.z + c2.z; P2.w = l2.w + c2.w;
    }

    float4 v;
    v.x = e1 * (tot.x - P1.x) + e2 * P2.x;
    v.y = e1 * (tot.y - P1.y) + e2 * P2.y;
    v.z = e1 * (tot.z - P1.z) + e2 * P2.z;
    v.w = e1 * (tot.w - P1.w) + e2 * P2.w;
    v.x = v.x > 0.f ? v.x : expm1f(v.x);
    v.y = v.y > 0.f ? v.y : expm1f(v.y);
    v.z = v.z > 0.f ? v.z : expm1f(v.z);
    v.w = v.w > 0.f ? v.w : expm1f(v.w);

    *(float4*)&out[(size_t)gq * D + d4] = v;
}

// -----------------------------------------------------------------------------
extern "C" void kernel_launch(void* const* d_in, const int* in_sizes, int n_in,
                              void* d_out, int out_size)
{
    const float* h = (const float*)d_in[0];   // [8,2048,256]
    const float* W = (const float*)d_in[1];   // [256,128]
    const float* a = (const float*)d_in[2];   // [256,1]
    float* out = (float*)d_out;               // [8,2048,128]

    k_gemm <<<(B * NTOK) / 128, 256>>>(h, W, a);
    k_sort <<<dim3(2, B), 1024>>>();
    k_gfill<<<dim3(NTOK / 256, B), 256>>>();
    k_scan <<<dim3(NCHUNK, B), 128>>>();
    k_coff <<<B, 1024>>>();
    k_out  <<<(B * NTOK) / 8, 256>>>(out);
}

// round 5
// speedup vs baseline: 2.0264x; 1.0533x over previous
#include <cuda_runtime.h>
#include <cuda_bf16.h>
#include <math.h>
#include <stdint.h>

#define B    8
#define NTOK 2048
#define FIN  256
#define D    128
#define ALPHA 0.2f
#define CHUNK  16
#define NCHUNK (NTOK/CHUNK)   // 128

// ---------------- scratch (__device__ globals) --------------------------------
__device__ float d_Wh[B*NTOK*D];
__device__ float d_s1[B*NTOK];
__device__ float d_s2[B*NTOK];
__device__ float d_ss1[B*NTOK];
__device__ float d_pe[B*NTOK];
__device__ float d_pa[B*NTOK];
__device__ float d_s2s[B*NTOK];
__device__ int   d_perm[B*NTOK];
__device__ float d_g1[B*NTOK];
__device__ float d_g2[B*NTOK];
__device__ int   d_tq[B*NTOK];
__device__ float d_e1[B*NTOK];
__device__ float d_e2[B*NTOK];
__device__ float d_loc1[B*NTOK*D];
__device__ float d_loc2[B*NTOK*D];
__device__ float d_ct1[B*NCHUNK*D];
__device__ float d_ct2[B*NCHUNK*D];
__device__ float d_cp1[B*NCHUNK*D];
__device__ float d_cp2[B*NCHUNK*D];
__device__ float d_tot1[B*D];

// ================= mma.sync helpers ============================================
__device__ __forceinline__ uint32_t smem_u32(const void* p) {
    uint32_t a;
    asm("{ .reg .u64 t; cvta.to.shared.u64 t, %1; cvt.u32.u64 %0, t; }" : "=r"(a) : "l"(p));
    return a;
}
__device__ __forceinline__ void ldm_x4(uint32_t& r0, uint32_t& r1, uint32_t& r2, uint32_t& r3, uint32_t addr) {
    asm volatile("ldmatrix.sync.aligned.m8n8.x4.shared.b16 {%0,%1,%2,%3}, [%4];"
        : "=r"(r0), "=r"(r1), "=r"(r2), "=r"(r3) : "r"(addr));
}
__device__ __forceinline__ void mma_bf16(float* c, const uint32_t* a, const uint32_t* b) {
    asm volatile("mma.sync.aligned.m16n8k16.row.col.f32.bf16.bf16.f32 "
        "{%0,%1,%2,%3},{%4,%5,%6,%7},{%8,%9},{%0,%1,%2,%3};"
        : "+f"(c[0]), "+f"(c[1]), "+f"(c[2]), "+f"(c[3])
        : "r"(a[0]), "r"(a[1]), "r"(a[2]), "r"(a[3]), "r"(b[0]), "r"(b[1]));
}

// smem layout (bytes). Rows padded to 72 bf16 (144 B) => ldmatrix bank step 4.
#define KT      64
#define ROWB    144
#define AH_OFF  0
#define AL_OFF  18432
#define BH_OFF  36864
#define BL_OFF  55296
#define A1_OFF  73728
#define A2_OFF  74240
#define PS1_OFF 74752
#define PS2_OFF 75264
#define SM_TOT  75776

// ---------------- K1: Wh = h@W via mma.sync bf16x3, fused s1/s2 ---------------
__global__ void __launch_bounds__(256, 1)
k_gemm_mma(const float* __restrict__ h, const float* __restrict__ W,
           const float* __restrict__ a)
{
    extern __shared__ char smem[];
    const uint32_t sb = smem_u32(smem);
    const int tid  = threadIdx.x;
    const int wid  = tid >> 5;
    const int lane = tid & 31;
    const int rowBase = blockIdx.x * 128;

    float* a1s = (float*)(smem + A1_OFF);
    float* a2s = (float*)(smem + A2_OFF);
    float* ps1 = (float*)(smem + PS1_OFF);
    float* ps2 = (float*)(smem + PS2_OFF);

    if (tid < 128) {
        a1s[tid] = a[tid];
        a2s[tid] = a[128 + tid];
        ps1[tid] = 0.f;
        ps2[tid] = 0.f;
    }

    const int mb0 = (wid & 3) * 32;        // warp row block (2 m16 tiles)
    const int nb  = (wid >> 2) * 64;       // warp col block (8 n8 tiles)

    float acc[2][8][4] = {};

    for (int t = 0; t < 4; t++) {
        const int kt = t * KT;
        __syncthreads();                   // protect smem reuse across tiles

        // ---- stage A: h[rowBase..+127][kt..+63] -> bf16 hi/lo, padded rows
        #pragma unroll
        for (int l = 0; l < 8; l++) {
            int f4 = tid + l * 256;        // 0..2047, 16 float4 per row
            int r  = f4 >> 4;
            int c  = (f4 & 15) * 4;
            float4 v = *(const float4*)&h[(size_t)(rowBase + r) * FIN + kt + c];
            __nv_bfloat162 h0 = __floats2bfloat162_rn(v.x, v.y);
            __nv_bfloat162 h1 = __floats2bfloat162_rn(v.z, v.w);
            __nv_bfloat162 l0 = __floats2bfloat162_rn(v.x - __bfloat162float(h0.x),
                                                      v.y - __bfloat162float(h0.y));
            __nv_bfloat162 l1 = __floats2bfloat162_rn(v.z - __bfloat162float(h1.x),
                                                      v.w - __bfloat162float(h1.y));
            uint32_t off = (uint32_t)r * ROWB + (uint32_t)c * 2;
            *(uint2*)(smem + AH_OFF + off) = make_uint2(*(uint32_t*)&h0, *(uint32_t*)&h1);
            *(uint2*)(smem + AL_OFF + off) = make_uint2(*(uint32_t*)&l0, *(uint32_t*)&l1);
        }
        // ---- stage B transposed: Bs[n][k] = W[kt+k][n] -> bf16 hi/lo
        #pragma unroll
        for (int l = 0; l < 8; l++) {
            int f4 = tid + l * 256;        // 0..2047, 32 float4 per k-row
            int k  = f4 >> 5;
            int n0 = (f4 & 31) * 4;
            float4 v = *(const float4*)&W[(size_t)(kt + k) * D + n0];
            #pragma unroll
            for (int j = 0; j < 4; j++) {
                float x = (j == 0 ? v.x : j == 1 ? v.y : j == 2 ? v.z : v.w);
                __nv_bfloat16 hi = __float2bfloat16_rn(x);
                __nv_bfloat16 lo = __float2bfloat16_rn(x - __bfloat162float(hi));
                uint32_t off = (uint32_t)(n0 + j) * ROWB + (uint32_t)k * 2;
                *(__nv_bfloat16*)(smem + BH_OFF + off) = hi;
                *(__nv_bfloat16*)(smem + BL_OFF + off) = lo;
            }
        }
        __syncthreads();

        #pragma unroll
        for (int ks = 0; ks < 4; ks++) {
            const uint32_t colB = (uint32_t)ks * 32 + (uint32_t)(lane >> 4) * 16;

            uint32_t a_hi[2][4], a_lo[2][4];
            #pragma unroll
            for (int mt = 0; mt < 2; mt++) {
                uint32_t roff = (uint32_t)(mb0 + mt * 16 + (lane & 15)) * ROWB + colB;
                ldm_x4(a_hi[mt][0], a_hi[mt][1], a_hi[mt][2], a_hi[mt][3], sb + AH_OFF + roff);
                ldm_x4(a_lo[mt][0], a_lo[mt][1], a_lo[mt][2], a_lo[mt][3], sb + AL_OFF + roff);
            }
            uint32_t b_hi[8][2], b_lo[8][2];
            #pragma unroll
            for (int g = 0; g < 4; g++) {
                uint32_t roff = (uint32_t)(nb + g * 16 + (lane & 15)) * ROWB + colB;
                ldm_x4(b_hi[g*2][0], b_hi[g*2+1][0], b_hi[g*2][1], b_hi[g*2+1][1], sb + BH_OFF + roff);
                ldm_x4(b_lo[g*2][0], b_lo[g*2+1][0], b_lo[g*2][1], b_lo[g*2+1][1], sb + BL_OFF + roff);
            }
            #pragma unroll
            for (int mt = 0; mt < 2; mt++)
                #pragma unroll
                for (int nt = 0; nt < 8; nt++) {
                    mma_bf16(acc[mt][nt], a_hi[mt], b_hi[nt]);
                    mma_bf16(acc[mt][nt], a_hi[mt], b_lo[nt]);
                    mma_bf16(acc[mt][nt], a_lo[mt], b_hi[nt]);
                }
        }
    }
    __syncthreads();

    // ---- epilogue: store Wh, fused s1/s2 row dots via smem atomics ----
    #pragma unroll
    for (int mt = 0; mt < 2; mt++) {
        const int r0 = mb0 + mt * 16 + (lane >> 2);
        const int r1 = r0 + 8;
        float p1a = 0.f, p2a = 0.f, p1b = 0.f, p2b = 0.f;
        #pragma unroll
        for (int nt = 0; nt < 8; nt++) {
            const int col = nb + nt * 8 + (lane & 3) * 2;
            float c0 = acc[mt][nt][0], c1 = acc[mt][nt][1];
            float c2 = acc[mt][nt][2], c3 = acc[mt][nt][3];
            *(float2*)&d_Wh[(size_t)(rowBase + r0) * D + col] = make_float2(c0, c1);
            *(float2*)&d_Wh[(size_t)(rowBase + r1) * D + col] = make_float2(c2, c3);
            p1a += c0 * a1s[col] + c1 * a1s[col + 1];
            p2a += c0 * a2s[col] + c1 * a2s[col + 1];
            p1b += c2 * a1s[col] + c3 * a1s[col + 1];
            p2b += c2 * a2s[col] + c3 * a2s[col + 1];
        }
        #pragma unroll
        for (int o = 1; o <= 2; o <<= 1) {
            p1a += __shfl_xor_sync(0xffffffffu, p1a, o);
            p2a += __shfl_xor_sync(0xffffffffu, p2a, o);
            p1b += __shfl_xor_sync(0xffffffffu, p1b, o);
            p2b += __shfl_xor_sync(0xffffffffu, p2b, o);
        }
        if ((lane & 3) == 0) {
            atomicAdd(&ps1[r0], p1a);
            atomicAdd(&ps2[r0], p2a);
            atomicAdd(&ps1[r1], p1b);
            atomicAdd(&ps2[r1], p2b);
        }
    }
    __syncthreads();
    if (tid < 128) {
        d_s1[rowBase + tid] = ps1[tid];
        d_s2[rowBase + tid] = ps2[tid];
    }
}

// ------- K2a: bitonic sort. role 0: s1 + exp-prefix scans; role 1: s2 + perm --
__global__ void __launch_bounds__(1024) k_sort()
{
    __shared__ float key[NTOK];
    __shared__ int   idx[NTOK];
    __shared__ float pe[NTOK];
    __shared__ float pa[NTOK];

    const int role = blockIdx.x, b = blockIdx.y, tid = threadIdx.x;
    const float* src = (role == 0 ? d_s1 : d_s2) + b * NTOK;

    key[tid] = src[tid];  key[tid + 1024] = src[tid + 1024];
    idx[tid] = tid;       idx[tid + 1024] = tid + 1024;
    __syncthreads();

    for (int k = 2; k <= NTOK; k <<= 1) {
        for (int j = k >> 1; j > 0; j >>= 1) {
            #pragma unroll
            for (int t = 0; t < 2; t++) {
                int i   = tid + t * 1024;
                int ixj = i ^ j;
                if (ixj > i) {
                    bool up = ((i & k) == 0);
                    float A = key[i], Bv = key[ixj];
                    if ((A > Bv) == up) {
                        key[i] = Bv; key[ixj] = A;
                        int tp = idx[i]; idx[i] = idx[ixj]; idx[ixj] = tp;
                    }
                }
            }
            __syncthreads();
        }
    }

    if (role == 1) {
        d_s2s[b * NTOK + tid]         = key[tid];
        d_s2s[b * NTOK + tid + 1024]  = key[tid + 1024];
        d_perm[b * NTOK + tid]        = idx[tid];
        d_perm[b * NTOK + tid + 1024] = idx[tid + 1024];
        return;
    }

    pe[tid]        = expf(key[tid]);
    pe[tid + 1024] = expf(key[tid + 1024]);
    pa[tid]        = expf(ALPHA * key[tid]);
    pa[tid + 1024] = expf(ALPHA * key[tid + 1024]);
    __syncthreads();

    for (int off = 1; off < NTOK; off <<= 1) {
        float v0e = pe[tid] + (tid >= off ? pe[tid - off] : 0.f);
        float v0a = pa[tid] + (tid >= off ? pa[tid - off] : 0.f);
        int i1 = tid + 1024;
        float v1e = pe[i1] + pe[i1 - off];
        float v1a = pa[i1] + pa[i1 - off];
        __syncthreads();
        pe[tid] = v0e; pa[tid] = v0a; pe[i1] = v1e; pa[i1] = v1a;
        __syncthreads();
    }

    d_ss1[b * NTOK + tid]        = key[tid];
    d_ss1[b * NTOK + tid + 1024] = key[tid + 1024];
    d_pe[b * NTOK + tid]         = pe[tid];
    d_pe[b * NTOK + tid + 1024]  = pe[tid + 1024];
    d_pa[b * NTOK + tid]         = pa[tid];
    d_pa[b * NTOK + tid + 1024]  = pa[tid + 1024];
}

// ------- K2b: per-j g1/g2 + per-i threshold/exps ------------------------------
__global__ void __launch_bounds__(256) k_gfill()
{
    __shared__ float ss1[NTOK];
    __shared__ float ss2[NTOK];

    const int b = blockIdx.y, tid = threadIdx.x;
    const int base = blockIdx.x * 256;

    #pragma unroll
    for (int l = 0; l < 2; l++) {
        int f4 = tid + l * 256;
        *(float4*)&ss1[f4 * 4] = *(const float4*)&d_ss1[b * NTOK + f4 * 4];
        *(float4*)&ss2[f4 * 4] = *(const float4*)&d_s2s[b * NTOK + f4 * 4];
    }
    __syncthreads();

    const float totE = d_pe[b * NTOK + NTOK - 1];

    {
        int jj = base + tid;
        float s2v = ss2[jj];
        float keyv = -s2v;
        int lo = 0, hi = NTOK;
        while (lo < hi) { int mid = (lo + hi) >> 1; if (ss1[mid] < keyv) lo = mid + 1; else hi = mid; }
        float preE = lo > 0 ? d_pe[b * NTOK + lo - 1] : 0.f;
        float preA = lo > 0 ? d_pa[b * NTOK + lo - 1] : 0.f;
        float e2  = expf(s2v);
        float ea2 = expf(ALPHA * s2v);
        float inv = 1.f / (e2 * (totE - preE) + ea2 * preA);
        d_g1[b * NTOK + jj] = e2  * inv;
        d_g2[b * NTOK + jj] = ea2 * inv;
    }
    {
        int i = base + tid;
        float s1v = d_s1[b * NTOK + i];
        float keyv = -s1v;
        int lo = 0, hi = NTOK;
        while (lo < hi) { int mid = (lo + hi) >> 1; if (ss2[mid] < keyv) lo = mid + 1; else hi = mid; }
        d_tq[b * NTOK + i] = lo;
        d_e1[b * NTOK + i] = expf(s1v);
        d_e2[b * NTOK + i] = expf(ALPHA * s1v);
    }
}

// ------- K3: chunk-local prefix sums (reg-batched gather, CHUNK=16) -----------
__global__ void __launch_bounds__(128) k_scan()
{
    __shared__ int   sp[CHUNK];
    __shared__ float sg1[CHUNK], sg2[CHUNK];

    const int b = blockIdx.y, c = blockIdx.x, d = threadIdx.x;
    const int base = b * NTOK + c * CHUNK;

    if (d < CHUNK)           sp [d]             = d_perm[base + d];
    else if (d < 2 * CHUNK)  sg1[d - CHUNK]     = d_g1[base + d - CHUNK];
    else if (d < 3 * CHUNK)  sg2[d - 2 * CHUNK] = d_g2[base + d - 2 * CHUNK];
    __syncthreads();

    float w[CHUNK];
    #pragma unroll
    for (int r = 0; r < CHUNK; r++)
        w[r] = d_Wh[((size_t)b * NTOK + sp[r]) * D + d];

    float s1a = 0.f, s2a = 0.f;
    #pragma unroll
    for (int r = 0; r < CHUNK; r++) {
        s1a += sg1[r] * w[r];
        s2a += sg2[r] * w[r];
        d_loc1[(size_t)(base + r) * D + d] = s1a;
        d_loc2[(size_t)(base + r) * D + d] = s2a;
    }
    d_ct1[(b * NCHUNK + c) * D + d] = s1a;
    d_ct2[(b * NCHUNK + c) * D + d] = s2a;
}

// ------- K4: two-phase exclusive scan of 128 chunk totals ---------------------
__global__ void __launch_bounds__(1024) k_coff()
{
    __shared__ float part1[8][D];
    __shared__ float part2[8][D];

    const int b = blockIdx.x;
    const int d = threadIdx.x & 127;
    const int g = threadIdx.x >> 7;

    float v1[16], v2[16];
    #pragma unroll
    for (int r = 0; r < 16; r++) {
        int c = g * 16 + r;
        v1[r] = d_ct1[(b * NCHUNK + c) * D + d];
        v2[r] = d_ct2[(b * NCHUNK + c) * D + d];
    }
    float run1 = 0.f, run2 = 0.f;
    #pragma unroll
    for (int r = 0; r < 16; r++) {
        float t1 = v1[r]; v1[r] = run1; run1 += t1;
        float t2 = v2[r]; v2[r] = run2; run2 += t2;
    }
    part1[g][d] = run1;
    part2[g][d] = run2;
    __syncthreads();

    if (g == 0) {
        float r1 = 0.f, r2 = 0.f;
        #pragma unroll
        for (int gg = 0; gg < 8; gg++) {
            float t1 = part1[gg][d]; part1[gg][d] = r1; r1 += t1;
            float t2 = part2[gg][d]; part2[gg][d] = r2; r2 += t2;
        }
        d_tot1[b * D + d] = r1;
    }
    __syncthreads();

    const float o1 = part1[g][d];
    const float o2 = part2[g][d];
    #pragma unroll
    for (int r = 0; r < 16; r++) {
        int c = g * 16 + r;
        d_cp1[(b * NCHUNK + c) * D + d] = o1 + v1[r];
        d_cp2[(b * NCHUNK + c) * D + d] = o2 + v2[r];
    }
}

// ------- K5: wide gather + ELU -------------------------------------------------
__global__ void __launch_bounds__(256) k_out(float* __restrict__ out)
{
    const int gq   = blockIdx.x * 8 + (threadIdx.x >> 5);
    const int lane = threadIdx.x & 31;
    const int b    = gq >> 11;
    const int d4   = lane * 4;

    const int   t  = d_tq[gq];
    const float e1 = d_e1[gq];
    const float e2 = d_e2[gq];

    float4 tot = *(const float4*)&d_tot1[b * D + d4];
    float4 P1 = {0.f, 0.f, 0.f, 0.f};
    float4 P2 = {0.f, 0.f, 0.f, 0.f};

    if (t > 0) {
        int k = t - 1;
        int c = k >> 4;
        size_t kb = (size_t)(b * NTOK + k) * D + d4;
        size_t cb = (size_t)(b * NCHUNK + c) * D + d4;
        float4 l1 = *(const float4*)&d_loc1[kb];
        float4 l2 = *(const float4*)&d_loc2[kb];
        float4 c1 = *(const float4*)&d_cp1[cb];
        float4 c2 = *(const float4*)&d_cp2[cb];
        P1.x = l1.x + c1.x; P1.y = l1.y + c1.y; P1.z = l1.z + c1.z; P1.w = l1.w + c1.w;
        P2.x = l2.x + c2.x; P2.y = l2.y + c2.y; P2.z = l2.z + c2.z; P2.w = l2.w + c2.w;
    }

    float4 v;
    v.x = e1 * (tot.x - P1.x) + e2 * P2.x;
    v.y = e1 * (tot.y - P1.y) + e2 * P2.y;
    v.z = e1 * (tot.z - P1.z) + e2 * P2.z;
    v.w = e1 * (tot.w - P1.w) + e2 * P2.w;
    v.x = v.x > 0.f ? v.x : expm1f(v.x);
    v.y = v.y > 0.f ? v.y : expm1f(v.y);
    v.z = v.z > 0.f ? v.z : expm1f(v.z);
    v.w = v.w > 0.f ? v.w : expm1f(v.w);

    *(float4*)&out[(size_t)gq * D + d4] = v;
}

// -----------------------------------------------------------------------------
extern "C" void kernel_launch(void* const* d_in, const int* in_sizes, int n_in,
                              void* d_out, int out_size)
{
    const float* h = (const float*)d_in[0];   // [8,2048,256]
    const float* W = (const float*)d_in[1];   // [256,128]
    const float* a = (const float*)d_in[2];   // [256,1]
    float* out = (float*)d_out;               // [8,2048,128]

    cudaFuncSetAttribute(k_gemm_mma, cudaFuncAttributeMaxDynamicSharedMemorySize, SM_TOT);

    k_gemm_mma<<<(B * NTOK) / 128, 256, SM_TOT>>>(h, W, a);
    k_sort <<<dim3(2, B), 1024>>>();
    k_gfill<<<dim3(NTOK / 256, B), 256>>>();
    k_scan <<<dim3(NCHUNK, B), 128>>>();
    k_coff <<<B, 1024>>>();
    k_out  <<<(B * NTOK) / 8, 256>>>(out);
}

// round 6
// speedup vs baseline: 2.4157x; 1.1921x over previous
#include <cuda_runtime.h>
#include <cuda_bf16.h>
#include <math.h>
#include <stdint.h>

#define B    8
#define NTOK 2048
#define FIN  256
#define D    128
#define ALPHA 0.2f
#define CHUNK  16
#define NCHUNK (NTOK/CHUNK)   // 128

// ---------------- scratch (__device__ globals) --------------------------------
__device__ float d_Wh[B*NTOK*D];
__device__ float d_s1[B*NTOK];
__device__ float d_s2[B*NTOK];
__device__ float d_ss1[B*NTOK];
__device__ float d_pe[B*NTOK];
__device__ float d_pa[B*NTOK];
__device__ float d_s2s[B*NTOK];
__device__ int   d_perm[B*NTOK];
__device__ float d_g1[B*NTOK];
__device__ float d_g2[B*NTOK];
__device__ int   d_tq[B*NTOK];
__device__ float d_e1[B*NTOK];
__device__ float d_e2[B*NTOK];
__device__ float d_loc1[B*NTOK*D];
__device__ float d_loc2[B*NTOK*D];
__device__ float d_ct1[B*NCHUNK*D];
__device__ float d_ct2[B*NCHUNK*D];
__device__ float d_cp1[B*NCHUNK*D];
__device__ float d_cp2[B*NCHUNK*D];
__device__ float d_tot1[B*D];

// ================= mma.sync helpers ============================================
__device__ __forceinline__ uint32_t smem_u32(const void* p) {
    uint32_t a;
    asm("{ .reg .u64 t; cvta.to.shared.u64 t, %1; cvt.u32.u64 %0, t; }" : "=r"(a) : "l"(p));
    return a;
}
__device__ __forceinline__ void ldm_x4(uint32_t& r0, uint32_t& r1, uint32_t& r2, uint32_t& r3, uint32_t addr) {
    asm volatile("ldmatrix.sync.aligned.m8n8.x4.shared.b16 {%0,%1,%2,%3}, [%4];"
        : "=r"(r0), "=r"(r1), "=r"(r2), "=r"(r3) : "r"(addr));
}
__device__ __forceinline__ void mma_bf16(float* c, const uint32_t* a, const uint32_t* b) {
    asm volatile("mma.sync.aligned.m16n8k16.row.col.f32.bf16.bf16.f32 "
        "{%0,%1,%2,%3},{%4,%5,%6,%7},{%8,%9},{%0,%1,%2,%3};"
        : "+f"(c[0]), "+f"(c[1]), "+f"(c[2]), "+f"(c[3])
        : "r"(a[0]), "r"(a[1]), "r"(a[2]), "r"(a[3]), "r"(b[0]), "r"(b[1]));
}

// smem layout (bytes). Rows padded to 72 bf16 (144 B) => ldmatrix bank step 4.
#define KT      64
#define ROWB    144
#define AH_OFF  0
#define AL_OFF  18432
#define BH_OFF  36864
#define BL_OFF  55296
#define A1_OFF  73728
#define A2_OFF  74240
#define PS1_OFF 74752
#define PS2_OFF 75264
#define SM_TOT  75776

// ---------------- K1: Wh = h@W via mma.sync bf16x3, fused s1/s2 ---------------
__global__ void __launch_bounds__(256, 1)
k_gemm_mma(const float* __restrict__ h, const float* __restrict__ W,
           const float* __restrict__ a)
{
    extern __shared__ char smem[];
    const uint32_t sb = smem_u32(smem);
    const int tid  = threadIdx.x;
    const int wid  = tid >> 5;
    const int lane = tid & 31;
    const int rowBase = blockIdx.x * 128;

    float* a1s = (float*)(smem + A1_OFF);
    float* a2s = (float*)(smem + A2_OFF);
    float* ps1 = (float*)(smem + PS1_OFF);
    float* ps2 = (float*)(smem + PS2_OFF);

    if (tid < 128) {
        a1s[tid] = a[tid];
        a2s[tid] = a[128 + tid];
        ps1[tid] = 0.f;
        ps2[tid] = 0.f;
    }

    const int mb0 = (wid & 3) * 32;
    const int nb  = (wid >> 2) * 64;

    float acc[2][8][4] = {};

    for (int t = 0; t < 4; t++) {
        const int kt = t * KT;
        __syncthreads();

        #pragma unroll
        for (int l = 0; l < 8; l++) {
            int f4 = tid + l * 256;
            int r  = f4 >> 4;
            int c  = (f4 & 15) * 4;
            float4 v = *(const float4*)&h[(size_t)(rowBase + r) * FIN + kt + c];
            __nv_bfloat162 h0 = __floats2bfloat162_rn(v.x, v.y);
            __nv_bfloat162 h1 = __floats2bfloat162_rn(v.z, v.w);
            __nv_bfloat162 l0 = __floats2bfloat162_rn(v.x - __bfloat162float(h0.x),
                                                      v.y - __bfloat162float(h0.y));
            __nv_bfloat162 l1 = __floats2bfloat162_rn(v.z - __bfloat162float(h1.x),
                                                      v.w - __bfloat162float(h1.y));
            uint32_t off = (uint32_t)r * ROWB + (uint32_t)c * 2;
            *(uint2*)(smem + AH_OFF + off) = make_uint2(*(uint32_t*)&h0, *(uint32_t*)&h1);
            *(uint2*)(smem + AL_OFF + off) = make_uint2(*(uint32_t*)&l0, *(uint32_t*)&l1);
        }
        #pragma unroll
        for (int l = 0; l < 8; l++) {
            int f4 = tid + l * 256;
            int k  = f4 >> 5;
            int n0 = (f4 & 31) * 4;
            float4 v = *(const float4*)&W[(size_t)(kt + k) * D + n0];
            #pragma unroll
            for (int j = 0; j < 4; j++) {
                float x = (j == 0 ? v.x : j == 1 ? v.y : j == 2 ? v.z : v.w);
                __nv_bfloat16 hi = __float2bfloat16_rn(x);
                __nv_bfloat16 lo = __float2bfloat16_rn(x - __bfloat162float(hi));
                uint32_t off = (uint32_t)(n0 + j) * ROWB + (uint32_t)k * 2;
                *(__nv_bfloat16*)(smem + BH_OFF + off) = hi;
                *(__nv_bfloat16*)(smem + BL_OFF + off) = lo;
            }
        }
        __syncthreads();

        #pragma unroll
        for (int ks = 0; ks < 4; ks++) {
            const uint32_t colB = (uint32_t)ks * 32 + (uint32_t)(lane >> 4) * 16;

            uint32_t a_hi[2][4], a_lo[2][4];
            #pragma unroll
            for (int mt = 0; mt < 2; mt++) {
                uint32_t roff = (uint32_t)(mb0 + mt * 16 + (lane & 15)) * ROWB + colB;
                ldm_x4(a_hi[mt][0], a_hi[mt][1], a_hi[mt][2], a_hi[mt][3], sb + AH_OFF + roff);
                ldm_x4(a_lo[mt][0], a_lo[mt][1], a_lo[mt][2], a_lo[mt][3], sb + AL_OFF + roff);
            }
            uint32_t b_hi[8][2], b_lo[8][2];
            #pragma unroll
            for (int g = 0; g < 4; g++) {
                uint32_t roff = (uint32_t)(nb + g * 16 + (lane & 15)) * ROWB + colB;
                ldm_x4(b_hi[g*2][0], b_hi[g*2+1][0], b_hi[g*2][1], b_hi[g*2+1][1], sb + BH_OFF + roff);
                ldm_x4(b_lo[g*2][0], b_lo[g*2+1][0], b_lo[g*2][1], b_lo[g*2+1][1], sb + BL_OFF + roff);
            }
            #pragma unroll
            for (int mt = 0; mt < 2; mt++)
                #pragma unroll
                for (int nt = 0; nt < 8; nt++) {
                    mma_bf16(acc[mt][nt], a_hi[mt], b_hi[nt]);
                    mma_bf16(acc[mt][nt], a_hi[mt], b_lo[nt]);
                    mma_bf16(acc[mt][nt], a_lo[mt], b_hi[nt]);
                }
        }
    }
    __syncthreads();

    #pragma unroll
    for (int mt = 0; mt < 2; mt++) {
        const int r0 = mb0 + mt * 16 + (lane >> 2);
        const int r1 = r0 + 8;
        float p1a = 0.f, p2a = 0.f, p1b = 0.f, p2b = 0.f;
        #pragma unroll
        for (int nt = 0; nt < 8; nt++) {
            const int col = nb + nt * 8 + (lane & 3) * 2;
            float c0 = acc[mt][nt][0], c1 = acc[mt][nt][1];
            float c2 = acc[mt][nt][2], c3 = acc[mt][nt][3];
            *(float2*)&d_Wh[(size_t)(rowBase + r0) * D + col] = make_float2(c0, c1);
            *(float2*)&d_Wh[(size_t)(rowBase + r1) * D + col] = make_float2(c2, c3);
            p1a += c0 * a1s[col] + c1 * a1s[col + 1];
            p2a += c0 * a2s[col] + c1 * a2s[col + 1];
            p1b += c2 * a1s[col] + c3 * a1s[col + 1];
            p2b += c2 * a2s[col] + c3 * a2s[col + 1];
        }
        #pragma unroll
        for (int o = 1; o <= 2; o <<= 1) {
            p1a += __shfl_xor_sync(0xffffffffu, p1a, o);
            p2a += __shfl_xor_sync(0xffffffffu, p2a, o);
            p1b += __shfl_xor_sync(0xffffffffu, p1b, o);
            p2b += __shfl_xor_sync(0xffffffffu, p2b, o);
        }
        if ((lane & 3) == 0) {
            atomicAdd(&ps1[r0], p1a);
            atomicAdd(&ps2[r0], p2a);
            atomicAdd(&ps1[r1], p1b);
            atomicAdd(&ps2[r1], p2b);
        }
    }
    __syncthreads();
    if (tid < 128) {
        d_s1[rowBase + tid] = ps1[tid];
        d_s2[rowBase + tid] = ps2[tid];
    }
}

// ------- K2a: hybrid register/shuffle bitonic sort -----------------------------
// role 0: s1 -> ss1 + exp-prefix scans (register warp scan)
// role 1: s2 -> s2s + perm
__global__ void __launch_bounds__(1024) k_sort()
{
    __shared__ float sk[NTOK];
    __shared__ int   sx[NTOK];
    __shared__ float wsum[64];

    const int role = blockIdx.x, b = blockIdx.y, tid = threadIdx.x;
    const int lane = tid & 31, wid = tid >> 5;
    const float* src = (role == 0 ? d_s1 : d_s2) + b * NTOK;

    float2 v0 = *(const float2*)&src[2 * tid];
    float k0 = v0.x, k1 = v0.y;
    int   x0 = 2 * tid, x1 = 2 * tid + 1;

    // ---- phase 1: k = 2..64, pure register/shuffle (no barriers) ----
    #pragma unroll
    for (int k = 2; k <= 64; k <<= 1) {
        const bool up = (((tid << 1) & k) == 0);
        #pragma unroll
        for (int j = k >> 1; j >= 2; j >>= 1) {
            const int m = j >> 1;
            float pk0 = __shfl_xor_sync(~0u, k0, m);
            float pk1 = __shfl_xor_sync(~0u, k1, m);
            int   px0 = __shfl_xor_sync(~0u, x0, m);
            int   px1 = __shfl_xor_sync(~0u, x1, m);
            const bool lo = ((tid & m) == 0);
            float lk = lo ? k0 : pk0, hk = lo ? pk0 : k0;
            if ((lk > hk) == up) { k0 = pk0; x0 = px0; }
            lk = lo ? k1 : pk1; hk = lo ? pk1 : k1;
            if ((lk > hk) == up) { k1 = pk1; x1 = px1; }
        }
        if ((k0 > k1) == up) {
            float tk = k0; k0 = k1; k1 = tk;
            int   tx = x0; x0 = x1; x1 = tx;
        }
    }

    // ---- phase 2: k = 128..2048, smem for j>=64, registers for tail ----
    #pragma unroll 1
    for (int k = 128; k <= 2048; k <<= 1) {
        sk[2 * tid] = k0; sk[2 * tid + 1] = k1;
        sx[2 * tid] = x0; sx[2 * tid + 1] = x1;
        __syncthreads();
        #pragma unroll 1
        for (int j = k >> 1; j >= 64; j >>= 1) {
            if ((tid & (j >> 1)) == 0) {
                const bool up = (((tid << 1) & k) == 0);
                #pragma unroll
                for (int bb = 0; bb < 2; bb++) {
                    int i = 2 * tid + bb, p = i ^ j;
                    float A = sk[i], Bv = sk[p];
                    if ((A > Bv) == up) {
                        sk[i] = Bv; sk[p] = A;
                        int tI = sx[i]; sx[i] = sx[p]; sx[p] = tI;
                    }
                }
            }
            __syncthreads();
        }
        k0 = sk[2 * tid]; k1 = sk[2 * tid + 1];
        x0 = sx[2 * tid]; x1 = sx[2 * tid + 1];
        const bool up = (((tid << 1) & k) == 0);
        #pragma unroll
        for (int j = 32; j >= 2; j >>= 1) {
            const int m = j >> 1;
            float pk0 = __shfl_xor_sync(~0u, k0, m);
            float pk1 = __shfl_xor_sync(~0u, k1, m);
            int   px0 = __shfl_xor_sync(~0u, x0, m);
            int   px1 = __shfl_xor_sync(~0u, x1, m);
            const bool lo = ((tid & m) == 0);
            float lk = lo ? k0 : pk0, hk = lo ? pk0 : k0;
            if ((lk > hk) == up) { k0 = pk0; x0 = px0; }
            lk = lo ? k1 : pk1; hk = lo ? pk1 : k1;
            if ((lk > hk) == up) { k1 = pk1; x1 = px1; }
        }
        if ((k0 > k1) == up) {
            float tk = k0; k0 = k1; k1 = tk;
            int   tx = x0; x0 = x1; x1 = tx;
        }
    }

    if (role == 1) {
        *(float2*)&d_s2s[b * NTOK + 2 * tid]  = make_float2(k0, k1);
        *(int2*)  &d_perm[b * NTOK + 2 * tid] = make_int2(x0, x1);
        return;
    }

    // ---- role 0: exp + inclusive prefix scans via register warp scan ----
    const float e0 = expf(k0), e1 = expf(k1);
    const float a0 = expf(ALPHA * k0), a1 = expf(ALPHA * k1);
    float ie = e0 + e1, ia = a0 + a1;
    const float se = ie, sa = ia;
    #pragma unroll
    for (int o = 1; o < 32; o <<= 1) {
        float te = __shfl_up_sync(~0u, ie, o);
        float ta = __shfl_up_sync(~0u, ia, o);
        if (lane >= o) { ie += te; ia += ta; }
    }
    if (lane == 31) { wsum[wid] = ie; wsum[32 + wid] = ia; }
    __syncthreads();
    if (wid == 0) {
        float we = wsum[lane], wa = wsum[32 + lane];
        #pragma unroll
        for (int o = 1; o < 32; o <<= 1) {
            float te = __shfl_up_sync(~0u, we, o);
            float ta = __shfl_up_sync(~0u, wa, o);
            if (lane >= o) { we += te; wa += ta; }
        }
        wsum[lane] = we; wsum[32 + lane] = wa;
    }
    __syncthreads();
    const float offE = (wid > 0 ? wsum[wid - 1] : 0.f);
    const float offA = (wid > 0 ? wsum[32 + wid - 1] : 0.f);
    const float peI = offE + ie;      // inclusive through element 2*tid+1
    const float paI = offA + ia;

    *(float2*)&d_ss1[b * NTOK + 2 * tid] = make_float2(k0, k1);
    *(float2*)&d_pe[b * NTOK + 2 * tid]  = make_float2(peI - e1, peI);
    *(float2*)&d_pa[b * NTOK + 2 * tid]  = make_float2(paI - a1, paI);
}

// ------- K2b: per-j g1/g2 + per-i threshold/exps ------------------------------
__global__ void __launch_bounds__(256) k_gfill()
{
    __shared__ float ss1[NTOK];
    __shared__ float ss2[NTOK];

    const int b = blockIdx.y, tid = threadIdx.x;
    const int base = blockIdx.x * 256;

    #pragma unroll
    for (int l = 0; l < 2; l++) {
        int f4 = tid + l * 256;
        *(float4*)&ss1[f4 * 4] = *(const float4*)&d_ss1[b * NTOK + f4 * 4];
        *(float4*)&ss2[f4 * 4] = *(const float4*)&d_s2s[b * NTOK + f4 * 4];
    }
    __syncthreads();

    const float totE = d_pe[b * NTOK + NTOK - 1];

    {
        int jj = base + tid;
        float s2v = ss2[jj];
        float keyv = -s2v;
        int lo = 0, hi = NTOK;
        while (lo < hi) { int mid = (lo + hi) >> 1; if (ss1[mid] < keyv) lo = mid + 1; else hi = mid; }
        float preE = lo > 0 ? d_pe[b * NTOK + lo - 1] : 0.f;
        float preA = lo > 0 ? d_pa[b * NTOK + lo - 1] : 0.f;
        float e2  = expf(s2v);
        float ea2 = expf(ALPHA * s2v);
        float inv = 1.f / (e2 * (totE - preE) + ea2 * preA);
        d_g1[b * NTOK + jj] = e2  * inv;
        d_g2[b * NTOK + jj] = ea2 * inv;
    }
    {
        int i = base + tid;
        float s1v = d_s1[b * NTOK + i];
        float keyv = -s1v;
        int lo = 0, hi = NTOK;
        while (lo < hi) { int mid = (lo + hi) >> 1; if (ss2[mid] < keyv) lo = mid + 1; else hi = mid; }
        d_tq[b * NTOK + i] = lo;
        d_e1[b * NTOK + i] = expf(s1v);
        d_e2[b * NTOK + i] = expf(ALPHA * s1v);
    }
}

// ------- K3: chunk-local prefix sums (reg-batched gather, CHUNK=16) -----------
__global__ void __launch_bounds__(128) k_scan()
{
    __shared__ int   sp[CHUNK];
    __shared__ float sg1[CHUNK], sg2[CHUNK];

    const int b = blockIdx.y, c = blockIdx.x, d = threadIdx.x;
    const int base = b * NTOK + c * CHUNK;

    if (d < CHUNK)           sp [d]             = d_perm[base + d];
    else if (d < 2 * CHUNK)  sg1[d - CHUNK]     = d_g1[base + d - CHUNK];
    else if (d < 3 * CHUNK)  sg2[d - 2 * CHUNK] = d_g2[base + d - 2 * CHUNK];
    __syncthreads();

    float w[CHUNK];
    #pragma unroll
    for (int r = 0; r < CHUNK; r++)
        w[r] = d_Wh[((size_t)b * NTOK + sp[r]) * D + d];

    float s1a = 0.f, s2a = 0.f;
    #pragma unroll
    for (int r = 0; r < CHUNK; r++) {
        s1a += sg1[r] * w[r];
        s2a += sg2[r] * w[r];
        d_loc1[(size_t)(base + r) * D + d] = s1a;
        d_loc2[(size_t)(base + r) * D + d] = s2a;
    }
    d_ct1[(b * NCHUNK + c) * D + d] = s1a;
    d_ct2[(b * NCHUNK + c) * D + d] = s2a;
}

// ------- K4: two-phase exclusive scan of 128 chunk totals ---------------------
__global__ void __launch_bounds__(1024) k_coff()
{
    __shared__ float part1[8][D];
    __shared__ float part2[8][D];

    const int b = blockIdx.x;
    const int d = threadIdx.x & 127;
    const int g = threadIdx.x >> 7;

    float v1[16], v2[16];
    #pragma unroll
    for (int r = 0; r < 16; r++) {
        int c = g * 16 + r;
        v1[r] = d_ct1[(b * NCHUNK + c) * D + d];
        v2[r] = d_ct2[(b * NCHUNK + c) * D + d];
    }
    float run1 = 0.f, run2 = 0.f;
    #pragma unroll
    for (int r = 0; r < 16; r++) {
        float t1 = v1[r]; v1[r] = run1; run1 += t1;
        float t2 = v2[r]; v2[r] = run2; run2 += t2;
    }
    part1[g][d] = run1;
    part2[g][d] = run2;
    __syncthreads();

    if (g == 0) {
        float r1 = 0.f, r2 = 0.f;
        #pragma unroll
        for (int gg = 0; gg < 8; gg++) {
            float t1 = part1[gg][d]; part1[gg][d] = r1; r1 += t1;
            float t2 = part2[gg][d]; part2[gg][d] = r2; r2 += t2;
        }
        d_tot1[b * D + d] = r1;
    }
    __syncthreads();

    const float o1 = part1[g][d];
    const float o2 = part2[g][d];
    #pragma unroll
    for (int r = 0; r < 16; r++) {
        int c = g * 16 + r;
        d_cp1[(b * NCHUNK + c) * D + d] = o1 + v1[r];
        d_cp2[(b * NCHUNK + c) * D + d] = o2 + v2[r];
    }
}

// ------- K5: wide gather + ELU -------------------------------------------------
__global__ void __launch_bounds__(256) k_out(float* __restrict__ out)
{
    const int gq   = blockIdx.x * 8 + (threadIdx.x >> 5);
    const int lane = threadIdx.x & 31;
    const int b    = gq >> 11;
    const int d4   = lane * 4;

    const int   t  = d_tq[gq];
    const float e1 = d_e1[gq];
    const float e2 = d_e2[gq];

    float4 tot = *(const float4*)&d_tot1[b * D + d4];
    float4 P1 = {0.f, 0.f, 0.f, 0.f};
    float4 P2 = {0.f, 0.f, 0.f, 0.f};

    if (t > 0) {
        int k = t - 1;
        int c = k >> 4;
        size_t kb = (size_t)(b * NTOK + k) * D + d4;
        size_t cb = (size_t)(b * NCHUNK + c) * D + d4;
        float4 l1 = *(const float4*)&d_loc1[kb];
        float4 l2 = *(const float4*)&d_loc2[kb];
        float4 c1 = *(const float4*)&d_cp1[cb];
        float4 c2 = *(const float4*)&d_cp2[cb];
        P1.x = l1.x + c1.x; P1.y = l1.y + c1.y; P1.z = l1.z + c1.z; P1.w = l1.w + c1.w;
        P2.x = l2.x + c2.x; P2.y = l2.y + c2.y; P2.z = l2.z + c2.z; P2.w = l2.w + c2.w;
    }

    float4 v;
    v.x = e1 * (tot.x - P1.x) + e2 * P2.x;
    v.y = e1 * (tot.y - P1.y) + e2 * P2.y;
    v.z = e1 * (tot.z - P1.z) + e2 * P2.z;
    v.w = e1 * (tot.w - P1.w) + e2 * P2.w;
    v.x = v.x > 0.f ? v.x : expm1f(v.x);
    v.y = v.y > 0.f ? v.y : expm1f(v.y);
    v.z = v.z > 0.f ? v.z : expm1f(v.z);
    v.w = v.w > 0.f ? v.w : expm1f(v.w);

    *(float4*)&out[(size_t)gq * D + d4] = v;
}

// -----------------------------------------------------------------------------
extern "C" void kernel_launch(void* const* d_in, const int* in_sizes, int n_in,
                              void* d_out, int out_size)
{
    const float* h = (const float*)d_in[0];   // [8,2048,256]
    const float* W = (const float*)d_in[1];   // [256,128]
    const float* a = (const float*)d_in[2];   // [256,1]
    float* out = (float*)d_out;               // [8,2048,128]

    cudaFuncSetAttribute(k_gemm_mma, cudaFuncAttributeMaxDynamicSharedMemorySize, SM_TOT);

    k_gemm_mma<<<(B * NTOK) / 128, 256, SM_TOT>>>(h, W, a);
    k_sort <<<dim3(2, B), 1024>>>();
    k_gfill<<<dim3(NTOK / 256, B), 256>>>();
    k_scan <<<dim3(NCHUNK, B), 128>>>();
    k_coff <<<B, 1024>>>();
    k_out  <<<(B * NTOK) / 8, 256>>>(out);
}

// round 7
// speedup vs baseline: 3.0955x; 1.2814x over previous
#include <cuda_runtime.h>
#include <cuda_bf16.h>
#include <math.h>
#include <stdint.h>

#define B    8
#define NTOK 2048
#define FIN  256
#define D    128
#define ALPHA 0.2f
#define CHUNK  16
#define NCHUNK (NTOK/CHUNK)   // 128

// ---------------- scratch (__device__ globals) --------------------------------
__device__ float d_Wh[B*NTOK*D];
__device__ float d_s1[B*NTOK];
__device__ float d_s2[B*NTOK];
__device__ float d_ss1[B*NTOK];
__device__ float d_pe[B*NTOK];
__device__ float d_pa[B*NTOK];
__device__ float d_s2s[B*NTOK];
__device__ int   d_perm[B*NTOK];
__device__ float d_g1[B*NTOK];
__device__ float d_g2[B*NTOK];
__device__ int   d_tq[B*NTOK];
__device__ float d_e1[B*NTOK];
__device__ float d_e2[B*NTOK];
__device__ float d_loc1[B*NTOK*D];
__device__ float d_loc2[B*NTOK*D];
__device__ float d_ct1[B*NCHUNK*D];
__device__ float d_ct2[B*NCHUNK*D];
__device__ float d_cp1[B*NCHUNK*D];
__device__ float d_cp2[B*NCHUNK*D];
__device__ float d_tot1[B*D];
__device__ __nv_bfloat16 d_Wt_hi[D*FIN];   // [n][k] transposed W, bf16 hi
__device__ __nv_bfloat16 d_Wt_lo[D*FIN];   // [n][k] residual lo

// ================= mma.sync helpers ============================================
__device__ __forceinline__ uint32_t smem_u32(const void* p) {
    uint32_t a;
    asm("{ .reg .u64 t; cvta.to.shared.u64 t, %1; cvt.u32.u64 %0, t; }" : "=r"(a) : "l"(p));
    return a;
}
__device__ __forceinline__ void ldm_x4(uint32_t& r0, uint32_t& r1, uint32_t& r2, uint32_t& r3, uint32_t addr) {
    asm volatile("ldmatrix.sync.aligned.m8n8.x4.shared.b16 {%0,%1,%2,%3}, [%4];"
        : "=r"(r0), "=r"(r1), "=r"(r2), "=r"(r3) : "r"(addr));
}
__device__ __forceinline__ void mma_bf16(float* c, const uint32_t* a, uint32_t b0, uint32_t b1) {
    asm volatile("mma.sync.aligned.m16n8k16.row.col.f32.bf16.bf16.f32 "
        "{%0,%1,%2,%3},{%4,%5,%6,%7},{%8,%9},{%0,%1,%2,%3};"
        : "+f"(c[0]), "+f"(c[1]), "+f"(c[2]), "+f"(c[3])
        : "r"(a[0]), "r"(a[1]), "r"(a[2]), "r"(a[3]), "r"(b0), "r"(b1));
}

// smem layout (bytes). Rows padded to 72 bf16 (144 B).
#define KT      64
#define ROWB    144
#define AH_OFF  0                      // 64 rows * 144
#define AL_OFF  9216
#define BH_OFF  18432                  // 128 rows * 144
#define BL_OFF  36864
#define A1_OFF  55296
#define A2_OFF  55808
#define PS1_OFF 56320                  // [2][64] floats
#define PS2_OFF 56832
#define SM_TOT  57344

// ---------------- K0: W -> bf16 hi/lo, transposed [n][k] ----------------------
__global__ void __launch_bounds__(256) k_wconv(const float* __restrict__ W)
{
    int idx = blockIdx.x * 256 + threadIdx.x;   // 0..32767
    int k = idx & 255;
    int n = idx >> 8;
    float x = W[(size_t)k * D + n];
    __nv_bfloat16 hi = __float2bfloat16_rn(x);
    __nv_bfloat16 lo = __float2bfloat16_rn(x - __bfloat162float(hi));
    d_Wt_hi[n * FIN + k] = hi;
    d_Wt_lo[n * FIN + k] = lo;
}

// ---------------- K1: Wh = h@W via mma.sync bf16x3 (64x128 tile) --------------
__global__ void __launch_bounds__(256, 2)
k_gemm_mma(const float* __restrict__ h, const float* __restrict__ a)
{
    extern __shared__ char smem[];
    const uint32_t sb = smem_u32(smem);
    const int tid  = threadIdx.x;
    const int wid  = tid >> 5;
    const int lane = tid & 31;
    const int rowBase = blockIdx.x * 64;

    float* a1s = (float*)(smem + A1_OFF);
    float* a2s = (float*)(smem + A2_OFF);
    float* ps1 = (float*)(smem + PS1_OFF);
    float* ps2 = (float*)(smem + PS2_OFF);

    if (tid < 128) {
        a1s[tid] = a[tid];
        a2s[tid] = a[128 + tid];
    }

    const int mb0 = (wid & 3) * 16;     // warp row block (one m16 tile)
    const int nbh = wid >> 2;           // col half 0/1
    const int nb  = nbh * 64;

    float acc[8][4] = {};

    for (int t = 0; t < 4; t++) {
        const int kt = t * KT;
        __syncthreads();

        // ---- stage A: h[rowBase..+63][kt..+63] -> bf16 hi/lo (1024 float4s)
        #pragma unroll
        for (int l = 0; l < 4; l++) {
            int f4 = tid + l * 256;
            int r  = f4 >> 4;
            int c  = (f4 & 15) * 4;
            float4 v = *(const float4*)&h[(size_t)(rowBase + r) * FIN + kt + c];
            __nv_bfloat162 h0 = __floats2bfloat162_rn(v.x, v.y);
            __nv_bfloat162 h1 = __floats2bfloat162_rn(v.z, v.w);
            __nv_bfloat162 l0 = __floats2bfloat162_rn(v.x - __bfloat162float(h0.x),
                                                      v.y - __bfloat162float(h0.y));
            __nv_bfloat162 l1 = __floats2bfloat162_rn(v.z - __bfloat162float(h1.x),
                                                      v.w - __bfloat162float(h1.y));
            uint32_t off = (uint32_t)r * ROWB + (uint32_t)c * 2;
            *(uint2*)(smem + AH_OFF + off) = make_uint2(*(uint32_t*)&h0, *(uint32_t*)&h1);
            *(uint2*)(smem + AL_OFF + off) = make_uint2(*(uint32_t*)&l0, *(uint32_t*)&l1);
        }
        // ---- stage B: copy preconverted W [n][kt..kt+63] (1024 uint4 per buf)
        #pragma unroll
        for (int l = 0; l < 4; l++) {
            int u  = tid + l * 256;
            int n  = u >> 3;
            int ch = (u & 7) * 16;      // byte chunk within 128B row
            uint32_t dst = (uint32_t)n * ROWB + (uint32_t)ch;
            const char* srch = (const char*)&d_Wt_hi[n * FIN + kt] + ch;
            const char* srcl = (const char*)&d_Wt_lo[n * FIN + kt] + ch;
            *(uint4*)(smem + BH_OFF + dst) = *(const uint4*)srch;
            *(uint4*)(smem + BL_OFF + dst) = *(const uint4*)srcl;
        }
        __syncthreads();

        #pragma unroll
        for (int ks = 0; ks < 4; ks++) {
            const uint32_t colB = (uint32_t)ks * 32 + (uint32_t)(lane >> 4) * 16;
            uint32_t a_hi[4], a_lo[4];
            {
                uint32_t roff = (uint32_t)(mb0 + (lane & 15)) * ROWB + colB;
                ldm_x4(a_hi[0], a_hi[1], a_hi[2], a_hi[3], sb + AH_OFF + roff);
                ldm_x4(a_lo[0], a_lo[1], a_lo[2], a_lo[3], sb + AL_OFF + roff);
            }
            #pragma unroll
            for (int g = 0; g < 4; g++) {
                uint32_t roff = (uint32_t)(nb + g * 16 + (lane & 15)) * ROWB + colB;
                uint32_t b0, b1, b2, b3;
                ldm_x4(b0, b1, b2, b3, sb + BH_OFF + roff);
                mma_bf16(acc[g * 2],     a_hi, b0, b2);
                mma_bf16(acc[g * 2 + 1], a_hi, b1, b3);
                mma_bf16(acc[g * 2],     a_lo, b0, b2);
                mma_bf16(acc[g * 2 + 1], a_lo, b1, b3);
                ldm_x4(b0, b1, b2, b3, sb + BL_OFF + roff);
                mma_bf16(acc[g * 2],     a_hi, b0, b2);
                mma_bf16(acc[g * 2 + 1], a_hi, b1, b3);
            }
        }
    }
    __syncthreads();

    // ---- epilogue: store Wh + fused s1/s2 (atomic-free) ----
    {
        const int r0 = mb0 + (lane >> 2);
        const int r1 = r0 + 8;
        float p1a = 0.f, p2a = 0.f, p1b = 0.f, p2b = 0.f;
        #pragma unroll
        for (int nt = 0; nt < 8; nt++) {
            const int col = nb + nt * 8 + (lane & 3) * 2;
            float c0 = acc[nt][0], c1 = acc[nt][1];
            float c2 = acc[nt][2], c3 = acc[nt][3];
            *(float2*)&d_Wh[(size_t)(rowBase + r0) * D + col] = make_float2(c0, c1);
            *(float2*)&d_Wh[(size_t)(rowBase + r1) * D + col] = make_float2(c2, c3);
            p1a += c0 * a1s[col] + c1 * a1s[col + 1];
            p2a += c0 * a2s[col] + c1 * a2s[col + 1];
            p1b += c2 * a1s[col] + c3 * a1s[col + 1];
            p2b += c2 * a2s[col] + c3 * a2s[col + 1];
        }
        #pragma unroll
        for (int o = 1; o <= 2; o <<= 1) {
            p1a += __shfl_xor_sync(0xffffffffu, p1a, o);
            p2a += __shfl_xor_sync(0xffffffffu, p2a, o);
            p1b += __shfl_xor_sync(0xffffffffu, p1b, o);
            p2b += __shfl_xor_sync(0xffffffffu, p2b, o);
        }
        if ((lane & 3) == 0) {
            ps1[nbh * 64 + r0] = p1a;  ps2[nbh * 64 + r0] = p2a;
            ps1[nbh * 64 + r1] = p1b;  ps2[nbh * 64 + r1] = p2b;
        }
    }
    __syncthreads();
    if (tid < 64) {
        d_s1[rowBase + tid] = ps1[tid] + ps1[64 + tid];
        d_s2[rowBase + tid] = ps2[tid] + ps2[64 + tid];
    }
}

// ------- K2a: hybrid register/shuffle bitonic sort -----------------------------
__global__ void __launch_bounds__(1024) k_sort()
{
    __shared__ float sk[NTOK];
    __shared__ int   sx[NTOK];
    __shared__ float wsum[64];

    const int role = blockIdx.x, b = blockIdx.y, tid = threadIdx.x;
    const int lane = tid & 31, wid = tid >> 5;
    const float* src = (role == 0 ? d_s1 : d_s2) + b * NTOK;

    float2 v0 = *(const float2*)&src[2 * tid];
    float k0 = v0.x, k1 = v0.y;
    int   x0 = 2 * tid, x1 = 2 * tid + 1;

    #pragma unroll
    for (int k = 2; k <= 64; k <<= 1) {
        const bool up = (((tid << 1) & k) == 0);
        #pragma unroll
        for (int j = k >> 1; j >= 2; j >>= 1) {
            const int m = j >> 1;
            float pk0 = __shfl_xor_sync(~0u, k0, m);
            float pk1 = __shfl_xor_sync(~0u, k1, m);
            int   px0 = __shfl_xor_sync(~0u, x0, m);
            int   px1 = __shfl_xor_sync(~0u, x1, m);
            const bool lo = ((tid & m) == 0);
            float lk = lo ? k0 : pk0, hk = lo ? pk0 : k0;
            if ((lk > hk) == up) { k0 = pk0; x0 = px0; }
            lk = lo ? k1 : pk1; hk = lo ? pk1 : k1;
            if ((lk > hk) == up) { k1 = pk1; x1 = px1; }
        }
        if ((k0 > k1) == up) {
            float tk = k0; k0 = k1; k1 = tk;
            int   tx = x0; x0 = x1; x1 = tx;
        }
    }

    #pragma unroll 1
    for (int k = 128; k <= 2048; k <<= 1) {
        sk[2 * tid] = k0; sk[2 * tid + 1] = k1;
        sx[2 * tid] = x0; sx[2 * tid + 1] = x1;
        __syncthreads();
        #pragma unroll 1
        for (int j = k >> 1; j >= 64; j >>= 1) {
            if ((tid & (j >> 1)) == 0) {
                const bool up = (((tid << 1) & k) == 0);
                #pragma unroll
                for (int bb = 0; bb < 2; bb++) {
                    int i = 2 * tid + bb, p = i ^ j;
                    float A = sk[i], Bv = sk[p];
                    if ((A > Bv) == up) {
                        sk[i] = Bv; sk[p] = A;
                        int tI = sx[i]; sx[i] = sx[p]; sx[p] = tI;
                    }
                }
            }
            __syncthreads();
        }
        k0 = sk[2 * tid]; k1 = sk[2 * tid + 1];
        x0 = sx[2 * tid]; x1 = sx[2 * tid + 1];
        const bool up = (((tid << 1) & k) == 0);
        #pragma unroll
        for (int j = 32; j >= 2; j >>= 1) {
            const int m = j >> 1;
            float pk0 = __shfl_xor_sync(~0u, k0, m);
            float pk1 = __shfl_xor_sync(~0u, k1, m);
            int   px0 = __shfl_xor_sync(~0u, x0, m);
            int   px1 = __shfl_xor_sync(~0u, x1, m);
            const bool lo = ((tid & m) == 0);
            float lk = lo ? k0 : pk0, hk = lo ? pk0 : k0;
            if ((lk > hk) == up) { k0 = pk0; x0 = px0; }
            lk = lo ? k1 : pk1; hk = lo ? pk1 : k1;
            if ((lk > hk) == up) { k1 = pk1; x1 = px1; }
        }
        if ((k0 > k1) == up) {
            float tk = k0; k0 = k1; k1 = tk;
            int   tx = x0; x0 = x1; x1 = tx;
        }
    }

    if (role == 1) {
        *(float2*)&d_s2s[b * NTOK + 2 * tid]  = make_float2(k0, k1);
        *(int2*)  &d_perm[b * NTOK + 2 * tid] = make_int2(x0, x1);
        return;
    }

    const float e0 = expf(k0), e1 = expf(k1);
    const float a0 = expf(ALPHA * k0), a1 = expf(ALPHA * k1);
    float ie = e0 + e1, ia = a0 + a1;
    #pragma unroll
    for (int o = 1; o < 32; o <<= 1) {
        float te = __shfl_up_sync(~0u, ie, o);
        float ta = __shfl_up_sync(~0u, ia, o);
        if (lane >= o) { ie += te; ia += ta; }
    }
    if (lane == 31) { wsum[wid] = ie; wsum[32 + wid] = ia; }
    __syncthreads();
    if (wid == 0) {
        float we = wsum[lane], wa = wsum[32 + lane];
        #pragma unroll
        for (int o = 1; o < 32; o <<= 1) {
            float te = __shfl_up_sync(~0u, we, o);
            float ta = __shfl_up_sync(~0u, wa, o);
            if (lane >= o) { we += te; wa += ta; }
        }
        wsum[lane] = we; wsum[32 + lane] = wa;
    }
    __syncthreads();
    const float offE = (wid > 0 ? wsum[wid - 1] : 0.f);
    const float offA = (wid > 0 ? wsum[32 + wid - 1] : 0.f);
    const float peI = offE + ie;
    const float paI = offA + ia;

    *(float2*)&d_ss1[b * NTOK + 2 * tid] = make_float2(k0, k1);
    *(float2*)&d_pe[b * NTOK + 2 * tid]  = make_float2(peI - e1, peI);
    *(float2*)&d_pa[b * NTOK + 2 * tid]  = make_float2(paI - a1, paI);
}

// ------- K2b: per-j g1/g2 + per-i threshold/exps ------------------------------
__global__ void __launch_bounds__(256) k_gfill()
{
    __shared__ float ss1[NTOK];
    __shared__ float ss2[NTOK];

    const int b = blockIdx.y, tid = threadIdx.x;
    const int base = blockIdx.x * 256;

    #pragma unroll
    for (int l = 0; l < 2; l++) {
        int f4 = tid + l * 256;
        *(float4*)&ss1[f4 * 4] = *(const float4*)&d_ss1[b * NTOK + f4 * 4];
        *(float4*)&ss2[f4 * 4] = *(const float4*)&d_s2s[b * NTOK + f4 * 4];
    }
    __syncthreads();

    const float totE = d_pe[b * NTOK + NTOK - 1];

    {
        int jj = base + tid;
        float s2v = ss2[jj];
        float keyv = -s2v;
        int lo = 0, hi = NTOK;
        while (lo < hi) { int mid = (lo + hi) >> 1; if (ss1[mid] < keyv) lo = mid + 1; else hi = mid; }
        float preE = lo > 0 ? d_pe[b * NTOK + lo - 1] : 0.f;
        float preA = lo > 0 ? d_pa[b * NTOK + lo - 1] : 0.f;
        float e2  = expf(s2v);
        float ea2 = expf(ALPHA * s2v);
        float inv = 1.f / (e2 * (totE - preE) + ea2 * preA);
        d_g1[b * NTOK + jj] = e2  * inv;
        d_g2[b * NTOK + jj] = ea2 * inv;
    }
    {
        int i = base + tid;
        float s1v = d_s1[b * NTOK + i];
        float keyv = -s1v;
        int lo = 0, hi = NTOK;
        while (lo < hi) { int mid = (lo + hi) >> 1; if (ss2[mid] < keyv) lo = mid + 1; else hi = mid; }
        d_tq[b * NTOK + i] = lo;
        d_e1[b * NTOK + i] = expf(s1v);
        d_e2[b * NTOK + i] = expf(ALPHA * s1v);
    }
}

// ------- K3: chunk-local prefix sums (reg-batched gather, CHUNK=16) -----------
__global__ void __launch_bounds__(128) k_scan()
{
    __shared__ int   sp[CHUNK];
    __shared__ float sg1[CHUNK], sg2[CHUNK];

    const int b = blockIdx.y, c = blockIdx.x, d = threadIdx.x;
    const int base = b * NTOK + c * CHUNK;

    if (d < CHUNK)           sp [d]             = d_perm[base + d];
    else if (d < 2 * CHUNK)  sg1[d - CHUNK]     = d_g1[base + d - CHUNK];
    else if (d < 3 * CHUNK)  sg2[d - 2 * CHUNK] = d_g2[base + d - 2 * CHUNK];
    __syncthreads();

    float w[CHUNK];
    #pragma unroll
    for (int r = 0; r < CHUNK; r++)
        w[r] = d_Wh[((size_t)b * NTOK + sp[r]) * D + d];

    float s1a = 0.f, s2a = 0.f;
    #pragma unroll
    for (int r = 0; r < CHUNK; r++) {
        s1a += sg1[r] * w[r];
        s2a += sg2[r] * w[r];
        d_loc1[(size_t)(base + r) * D + d] = s1a;
        d_loc2[(size_t)(base + r) * D + d] = s2a;
    }
    d_ct1[(b * NCHUNK + c) * D + d] = s1a;
    d_ct2[(b * NCHUNK + c) * D + d] = s2a;
}

// ------- K4: two-phase exclusive scan of 128 chunk totals ---------------------
__global__ void __launch_bounds__(1024) k_coff()
{
    __shared__ float part1[8][D];
    __shared__ float part2[8][D];

    const int b = blockIdx.x;
    const int d = threadIdx.x & 127;
    const int g = threadIdx.x >> 7;

    float v1[16], v2[16];
    #pragma unroll
    for (int r = 0; r < 16; r++) {
        int c = g * 16 + r;
        v1[r] = d_ct1[(b * NCHUNK + c) * D + d];
        v2[r] = d_ct2[(b * NCHUNK + c) * D + d];
    }
    float run1 = 0.f, run2 = 0.f;
    #pragma unroll
    for (int r = 0; r < 16; r++) {
        float t1 = v1[r]; v1[r] = run1; run1 += t1;
        float t2 = v2[r]; v2[r] = run2; run2 += t2;
    }
    part1[g][d] = run1;
    part2[g][d] = run2;
    __syncthreads();

    if (g == 0) {
        float r1 = 0.f, r2 = 0.f;
        #pragma unroll
        for (int gg = 0; gg < 8; gg++) {
            float t1 = part1[gg][d]; part1[gg][d] = r1; r1 += t1;
            float t2 = part2[gg][d]; part2[gg][d] = r2; r2 += t2;
        }
        d_tot1[b * D + d] = r1;
    }
    __syncthreads();

    const float o1 = part1[g][d];
    const float o2 = part2[g][d];
    #pragma unroll
    for (int r = 0; r < 16; r++) {
        int c = g * 16 + r;
        d_cp1[(b * NCHUNK + c) * D + d] = o1 + v1[r];
        d_cp2[(b * NCHUNK + c) * D + d] = o2 + v2[r];
    }
}

// ------- K5: wide gather + ELU -------------------------------------------------
__global__ void __launch_bounds__(256) k_out(float* __restrict__ out)
{
    const int gq   = blockIdx.x * 8 + (threadIdx.x >> 5);
    const int lane = threadIdx.x & 31;
    const int b    = gq >> 11;
    const int d4   = lane * 4;

    const int   t  = d_tq[gq];
    const float e1 = d_e1[gq];
    const float e2 = d_e2[gq];

    float4 tot = *(const float4*)&d_tot1[b * D + d4];
    float4 P1 = {0.f, 0.f, 0.f, 0.f};
    float4 P2 = {0.f, 0.f, 0.f, 0.f};

    if (t > 0) {
        int k = t - 1;
        int c = k >> 4;
        size_t kb = (size_t)(b * NTOK + k) * D + d4;
        size_t cb = (size_t)(b * NCHUNK + c) * D + d4;
        float4 l1 = *(const float4*)&d_loc1[kb];
        float4 l2 = *(const float4*)&d_loc2[kb];
        float4 c1 = *(const float4*)&d_cp1[cb];
        float4 c2 = *(const float4*)&d_cp2[cb];
        P1.x = l1.x + c1.x; P1.y = l1.y + c1.y; P1.z = l1.z + c1.z; P1.w = l1.w + c1.w;
        P2.x = l2.x + c2.x; P2.y = l2.y + c2.y; P2.z = l2.z + c2.z; P2.w = l2.w + c2.w;
    }

    float4 v;
    v.x = e1 * (tot.x - P1.x) + e2 * P2.x;
    v.y = e1 * (tot.y - P1.y) + e2 * P2.y;
    v.z = e1 * (tot.z - P1.z) + e2 * P2.z;
    v.w = e1 * (tot.w - P1.w) + e2 * P2.w;
    v.x = v.x > 0.f ? v.x : expm1f(v.x);
    v.y = v.y > 0.f ? v.y : expm1f(v.y);
    v.z = v.z > 0.f ? v.z : expm1f(v.z);
    v.w = v.w > 0.f ? v.w : expm1f(v.w);

    *(float4*)&out[(size_t)gq * D + d4] = v;
}

// -----------------------------------------------------------------------------
extern "C" void kernel_launch(void* const* d_in, const int* in_sizes, int n_in,
                              void* d_out, int out_size)
{
    const float* h = (const float*)d_in[0];   // [8,2048,256]
    const float* W = (const float*)d_in[1];   // [256,128]
    const float* a = (const float*)d_in[2];   // [256,1]
    float* out = (float*)d_out;               // [8,2048,128]

    cudaFuncSetAttribute(k_gemm_mma, cudaFuncAttributeMaxDynamicSharedMemorySize, SM_TOT);

    k_wconv<<<FIN * D / 256, 256>>>(W);
    k_gemm_mma<<<(B * NTOK) / 64, 256, SM_TOT>>>(h, a);
    k_sort <<<dim3(2, B), 1024>>>();
    k_gfill<<<dim3(NTOK / 256, B), 256>>>();
    k_scan <<<dim3(NCHUNK, B), 128>>>();
    k_coff <<<B, 1024>>>();
    k_out  <<<(B * NTOK) / 8, 256>>>(out);
}

// round 8
// speedup vs baseline: 3.0975x; 1.0006x over previous
#include <cuda_runtime.h>
#include <cuda_bf16.h>
#include <math.h>
#include <stdint.h>

#define B    8
#define NTOK 2048
#define FIN  256
#define D    128
#define ALPHA 0.2f
#define CHUNK  16
#define NCHUNK (NTOK/CHUNK)   // 128

// ---------------- scratch (__device__ globals) --------------------------------
__device__ float d_Wh[B*NTOK*D];
__device__ float d_s1[B*NTOK];
__device__ float d_s2[B*NTOK];
__device__ float d_ss1[B*NTOK];
__device__ float d_pe[B*NTOK];
__device__ float d_pa[B*NTOK];
__device__ float d_s2s[B*NTOK];
__device__ int   d_perm[B*NTOK];
__device__ float d_g1[B*NTOK];
__device__ float d_g2[B*NTOK];
__device__ int   d_tq[B*NTOK];
__device__ float d_e1[B*NTOK];
__device__ float d_e2[B*NTOK];
__device__ float d_loc12[B*NTOK*D*2];      // interleaved (v1,v2) prefix pairs
__device__ float d_ct1[B*NCHUNK*D];
__device__ float d_ct2[B*NCHUNK*D];
__device__ float d_cp12[B*NCHUNK*D*2];     // interleaved chunk offsets
__device__ float d_tot1[B*D];
__device__ __nv_bfloat16 d_Wt_hi[D*FIN];
__device__ __nv_bfloat16 d_Wt_lo[D*FIN];

// ================= mma.sync helpers ============================================
__device__ __forceinline__ uint32_t smem_u32(const void* p) {
    uint32_t a;
    asm("{ .reg .u64 t; cvta.to.shared.u64 t, %1; cvt.u32.u64 %0, t; }" : "=r"(a) : "l"(p));
    return a;
}
__device__ __forceinline__ void ldm_x4(uint32_t& r0, uint32_t& r1, uint32_t& r2, uint32_t& r3, uint32_t addr) {
    asm volatile("ldmatrix.sync.aligned.m8n8.x4.shared.b16 {%0,%1,%2,%3}, [%4];"
        : "=r"(r0), "=r"(r1), "=r"(r2), "=r"(r3) : "r"(addr));
}
__device__ __forceinline__ void mma_bf16(float* c, const uint32_t* a, uint32_t b0, uint32_t b1) {
    asm volatile("mma.sync.aligned.m16n8k16.row.col.f32.bf16.bf16.f32 "
        "{%0,%1,%2,%3},{%4,%5,%6,%7},{%8,%9},{%0,%1,%2,%3};"
        : "+f"(c[0]), "+f"(c[1]), "+f"(c[2]), "+f"(c[3])
        : "r"(a[0]), "r"(a[1]), "r"(a[2]), "r"(a[3]), "r"(b0), "r"(b1));
}

// smem layout (bytes). Rows padded to 72 bf16 (144 B).
#define KT      64
#define ROWB    144
#define AH_OFF  0
#define AL_OFF  9216
#define BH_OFF  18432
#define BL_OFF  36864
#define A1_OFF  55296
#define A2_OFF  55808
#define PS1_OFF 56320
#define PS2_OFF 56832
#define SM_TOT  57344

// ---------------- K0: W -> bf16 hi/lo, transposed [n][k] ----------------------
__global__ void __launch_bounds__(256) k_wconv(const float* __restrict__ W)
{
    int idx = blockIdx.x * 256 + threadIdx.x;
    int k = idx & 255;
    int n = idx >> 8;
    float x = W[(size_t)k * D + n];
    __nv_bfloat16 hi = __float2bfloat16_rn(x);
    __nv_bfloat16 lo = __float2bfloat16_rn(x - __bfloat162float(hi));
    d_Wt_hi[n * FIN + k] = hi;
    d_Wt_lo[n * FIN + k] = lo;
}

// ---------------- K1: Wh = h@W via mma.sync bf16x3 (64x128 tile) --------------
__global__ void __launch_bounds__(256, 2)
k_gemm_mma(const float* __restrict__ h, const float* __restrict__ a)
{
    extern __shared__ char smem[];
    const uint32_t sb = smem_u32(smem);
    const int tid  = threadIdx.x;
    const int wid  = tid >> 5;
    const int lane = tid & 31;
    const int rowBase = blockIdx.x * 64;

    float* a1s = (float*)(smem + A1_OFF);
    float* a2s = (float*)(smem + A2_OFF);
    float* ps1 = (float*)(smem + PS1_OFF);
    float* ps2 = (float*)(smem + PS2_OFF);

    if (tid < 128) {
        a1s[tid] = a[tid];
        a2s[tid] = a[128 + tid];
    }

    const int mb0 = (wid & 3) * 16;
    const int nbh = wid >> 2;
    const int nb  = nbh * 64;

    float acc[8][4] = {};

    for (int t = 0; t < 4; t++) {
        const int kt = t * KT;
        __syncthreads();

        #pragma unroll
        for (int l = 0; l < 4; l++) {
            int f4 = tid + l * 256;
            int r  = f4 >> 4;
            int c  = (f4 & 15) * 4;
            float4 v = *(const float4*)&h[(size_t)(rowBase + r) * FIN + kt + c];
            __nv_bfloat162 h0 = __floats2bfloat162_rn(v.x, v.y);
            __nv_bfloat162 h1 = __floats2bfloat162_rn(v.z, v.w);
            __nv_bfloat162 l0 = __floats2bfloat162_rn(v.x - __bfloat162float(h0.x),
                                                      v.y - __bfloat162float(h0.y));
            __nv_bfloat162 l1 = __floats2bfloat162_rn(v.z - __bfloat162float(h1.x),
                                                      v.w - __bfloat162float(h1.y));
            uint32_t off = (uint32_t)r * ROWB + (uint32_t)c * 2;
            *(uint2*)(smem + AH_OFF + off) = make_uint2(*(uint32_t*)&h0, *(uint32_t*)&h1);
            *(uint2*)(smem + AL_OFF + off) = make_uint2(*(uint32_t*)&l0, *(uint32_t*)&l1);
        }
        #pragma unroll
        for (int l = 0; l < 4; l++) {
            int u  = tid + l * 256;
            int n  = u >> 3;
            int ch = (u & 7) * 16;
            uint32_t dst = (uint32_t)n * ROWB + (uint32_t)ch;
            const char* srch = (const char*)&d_Wt_hi[n * FIN + kt] + ch;
            const char* srcl = (const char*)&d_Wt_lo[n * FIN + kt] + ch;
            *(uint4*)(smem + BH_OFF + dst) = *(const uint4*)srch;
            *(uint4*)(smem + BL_OFF + dst) = *(const uint4*)srcl;
        }
        __syncthreads();

        #pragma unroll
        for (int ks = 0; ks < 4; ks++) {
            const uint32_t colB = (uint32_t)ks * 32 + (uint32_t)(lane >> 4) * 16;
            uint32_t a_hi[4], a_lo[4];
            {
                uint32_t roff = (uint32_t)(mb0 + (lane & 15)) * ROWB + colB;
                ldm_x4(a_hi[0], a_hi[1], a_hi[2], a_hi[3], sb + AH_OFF + roff);
                ldm_x4(a_lo[0], a_lo[1], a_lo[2], a_lo[3], sb + AL_OFF + roff);
            }
            #pragma unroll
            for (int g = 0; g < 4; g++) {
                uint32_t roff = (uint32_t)(nb + g * 16 + (lane & 15)) * ROWB + colB;
                uint32_t b0, b1, b2, b3;
                ldm_x4(b0, b1, b2, b3, sb + BH_OFF + roff);
                mma_bf16(acc[g * 2],     a_hi, b0, b2);
                mma_bf16(acc[g * 2 + 1], a_hi, b1, b3);
                mma_bf16(acc[g * 2],     a_lo, b0, b2);
                mma_bf16(acc[g * 2 + 1], a_lo, b1, b3);
                ldm_x4(b0, b1, b2, b3, sb + BL_OFF + roff);
                mma_bf16(acc[g * 2],     a_hi, b0, b2);
                mma_bf16(acc[g * 2 + 1], a_hi, b1, b3);
            }
        }
    }
    __syncthreads();

    {
        const int r0 = mb0 + (lane >> 2);
        const int r1 = r0 + 8;
        float p1a = 0.f, p2a = 0.f, p1b = 0.f, p2b = 0.f;
        #pragma unroll
        for (int nt = 0; nt < 8; nt++) {
            const int col = nb + nt * 8 + (lane & 3) * 2;
            float c0 = acc[nt][0], c1 = acc[nt][1];
            float c2 = acc[nt][2], c3 = acc[nt][3];
            *(float2*)&d_Wh[(size_t)(rowBase + r0) * D + col] = make_float2(c0, c1);
            *(float2*)&d_Wh[(size_t)(rowBase + r1) * D + col] = make_float2(c2, c3);
            p1a += c0 * a1s[col] + c1 * a1s[col + 1];
            p2a += c0 * a2s[col] + c1 * a2s[col + 1];
            p1b += c2 * a1s[col] + c3 * a1s[col + 1];
            p2b += c2 * a2s[col] + c3 * a2s[col + 1];
        }
        #pragma unroll
        for (int o = 1; o <= 2; o <<= 1) {
            p1a += __shfl_xor_sync(0xffffffffu, p1a, o);
            p2a += __shfl_xor_sync(0xffffffffu, p2a, o);
            p1b += __shfl_xor_sync(0xffffffffu, p1b, o);
            p2b += __shfl_xor_sync(0xffffffffu, p2b, o);
        }
        if ((lane & 3) == 0) {
            ps1[nbh * 64 + r0] = p1a;  ps2[nbh * 64 + r0] = p2a;
            ps1[nbh * 64 + r1] = p1b;  ps2[nbh * 64 + r1] = p2b;
        }
    }
    __syncthreads();
    if (tid < 64) {
        d_s1[rowBase + tid] = ps1[tid] + ps1[64 + tid];
        d_s2[rowBase + tid] = ps2[tid] + ps2[64 + tid];
    }
}

// ------- K2a: hybrid register/shuffle bitonic sort -----------------------------
__global__ void __launch_bounds__(1024) k_sort()
{
    __shared__ float sk[NTOK];
    __shared__ int   sx[NTOK];
    __shared__ float wsum[64];

    const int role = blockIdx.x, b = blockIdx.y, tid = threadIdx.x;
    const int lane = tid & 31, wid = tid >> 5;
    const float* src = (role == 0 ? d_s1 : d_s2) + b * NTOK;

    float2 v0 = *(const float2*)&src[2 * tid];
    float k0 = v0.x, k1 = v0.y;
    int   x0 = 2 * tid, x1 = 2 * tid + 1;

    #pragma unroll
    for (int k = 2; k <= 64; k <<= 1) {
        const bool up = (((tid << 1) & k) == 0);
        #pragma unroll
        for (int j = k >> 1; j >= 2; j >>= 1) {
            const int m = j >> 1;
            float pk0 = __shfl_xor_sync(~0u, k0, m);
            float pk1 = __shfl_xor_sync(~0u, k1, m);
            int   px0 = __shfl_xor_sync(~0u, x0, m);
            int   px1 = __shfl_xor_sync(~0u, x1, m);
            const bool lo = ((tid & m) == 0);
            float lk = lo ? k0 : pk0, hk = lo ? pk0 : k0;
            if ((lk > hk) == up) { k0 = pk0; x0 = px0; }
            lk = lo ? k1 : pk1; hk = lo ? pk1 : k1;
            if ((lk > hk) == up) { k1 = pk1; x1 = px1; }
        }
        if ((k0 > k1) == up) {
            float tk = k0; k0 = k1; k1 = tk;
            int   tx = x0; x0 = x1; x1 = tx;
        }
    }

    #pragma unroll 1
    for (int k = 128; k <= 2048; k <<= 1) {
        sk[2 * tid] = k0; sk[2 * tid + 1] = k1;
        sx[2 * tid] = x0; sx[2 * tid + 1] = x1;
        __syncthreads();
        #pragma unroll 1
        for (int j = k >> 1; j >= 64; j >>= 1) {
            if ((tid & (j >> 1)) == 0) {
                const bool up = (((tid << 1) & k) == 0);
                #pragma unroll
                for (int bb = 0; bb < 2; bb++) {
                    int i = 2 * tid + bb, p = i ^ j;
                    float A = sk[i], Bv = sk[p];
                    if ((A > Bv) == up) {
                        sk[i] = Bv; sk[p] = A;
                        int tI = sx[i]; sx[i] = sx[p]; sx[p] = tI;
                    }
                }
            }
            __syncthreads();
        }
        k0 = sk[2 * tid]; k1 = sk[2 * tid + 1];
        x0 = sx[2 * tid]; x1 = sx[2 * tid + 1];
        const bool up = (((tid << 1) & k) == 0);
        #pragma unroll
        for (int j = 32; j >= 2; j >>= 1) {
            const int m = j >> 1;
            float pk0 = __shfl_xor_sync(~0u, k0, m);
            float pk1 = __shfl_xor_sync(~0u, k1, m);
            int   px0 = __shfl_xor_sync(~0u, x0, m);
            int   px1 = __shfl_xor_sync(~0u, x1, m);
            const bool lo = ((tid & m) == 0);
            float lk = lo ? k0 : pk0, hk = lo ? pk0 : k0;
            if ((lk > hk) == up) { k0 = pk0; x0 = px0; }
            lk = lo ? k1 : pk1; hk = lo ? pk1 : k1;
            if ((lk > hk) == up) { k1 = pk1; x1 = px1; }
        }
        if ((k0 > k1) == up) {
            float tk = k0; k0 = k1; k1 = tk;
            int   tx = x0; x0 = x1; x1 = tx;
        }
    }

    if (role == 1) {
        *(float2*)&d_s2s[b * NTOK + 2 * tid]  = make_float2(k0, k1);
        *(int2*)  &d_perm[b * NTOK + 2 * tid] = make_int2(x0, x1);
        return;
    }

    const float e0 = expf(k0), e1 = expf(k1);
    const float a0 = expf(ALPHA * k0), a1 = expf(ALPHA * k1);
    float ie = e0 + e1, ia = a0 + a1;
    #pragma unroll
    for (int o = 1; o < 32; o <<= 1) {
        float te = __shfl_up_sync(~0u, ie, o);
        float ta = __shfl_up_sync(~0u, ia, o);
        if (lane >= o) { ie += te; ia += ta; }
    }
    if (lane == 31) { wsum[wid] = ie; wsum[32 + wid] = ia; }
    __syncthreads();
    if (wid == 0) {
        float we = wsum[lane], wa = wsum[32 + lane];
        #pragma unroll
        for (int o = 1; o < 32; o <<= 1) {
            float te = __shfl_up_sync(~0u, we, o);
            float ta = __shfl_up_sync(~0u, wa, o);
            if (lane >= o) { we += te; wa += ta; }
        }
        wsum[lane] = we; wsum[32 + lane] = wa;
    }
    __syncthreads();
    const float offE = (wid > 0 ? wsum[wid - 1] : 0.f);
    const float offA = (wid > 0 ? wsum[32 + wid - 1] : 0.f);
    const float peI = offE + ie;
    const float paI = offA + ia;

    *(float2*)&d_ss1[b * NTOK + 2 * tid] = make_float2(k0, k1);
    *(float2*)&d_pe[b * NTOK + 2 * tid]  = make_float2(peI - e1, peI);
    *(float2*)&d_pa[b * NTOK + 2 * tid]  = make_float2(paI - a1, paI);
}

// ------- K2b: stagingless global binary searches -------------------------------
// grid (8, B, 2): z==0 -> j-side g1/g2; z==1 -> i-side threshold/exps
__global__ void __launch_bounds__(256) k_gfill()
{
    const int b = blockIdx.y;
    const int idx = blockIdx.x * 256 + threadIdx.x;    // 0..2047
    const float* ss1 = d_ss1 + b * NTOK;
    const float* ss2 = d_s2s + b * NTOK;

    if (blockIdx.z == 0) {
        float s2v = __ldg(&ss2[idx]);
        float keyv = -s2v;
        int lo = 0;
        #pragma unroll
        for (int step = 1024; step >= 1; step >>= 1) {
            int probe = lo + step - 1;                 // test if first 'step' more all < key
            if (probe < NTOK && __ldg(&ss1[probe]) < keyv) lo += step;
        }
        const float totE = __ldg(&d_pe[b * NTOK + NTOK - 1]);
        float preE = lo > 0 ? __ldg(&d_pe[b * NTOK + lo - 1]) : 0.f;
        float preA = lo > 0 ? __ldg(&d_pa[b * NTOK + lo - 1]) : 0.f;
        float e2  = expf(s2v);
        float ea2 = expf(ALPHA * s2v);
        float inv = 1.f / (e2 * (totE - preE) + ea2 * preA);
        d_g1[b * NTOK + idx] = e2  * inv;
        d_g2[b * NTOK + idx] = ea2 * inv;
    } else {
        float s1v = __ldg(&d_s1[b * NTOK + idx]);
        float keyv = -s1v;
        int lo = 0;
        #pragma unroll
        for (int step = 1024; step >= 1; step >>= 1) {
            int probe = lo + step - 1;
            if (probe < NTOK && __ldg(&ss2[probe]) < keyv) lo += step;
        }
        d_tq[b * NTOK + idx] = lo;
        d_e1[b * NTOK + idx] = expf(s1v);
        d_e2[b * NTOK + idx] = expf(ALPHA * s1v);
    }
}

// ------- K3: chunk-local prefix sums, interleaved STG.64 stores ----------------
__global__ void __launch_bounds__(128) k_scan()
{
    __shared__ int   sp[CHUNK];
    __shared__ float sg1[CHUNK], sg2[CHUNK];

    const int b = blockIdx.y, c = blockIdx.x, d = threadIdx.x;
    const int base = b * NTOK + c * CHUNK;

    if (d < CHUNK)           sp [d]             = d_perm[base + d];
    else if (d < 2 * CHUNK)  sg1[d - CHUNK]     = d_g1[base + d - CHUNK];
    else if (d < 3 * CHUNK)  sg2[d - 2 * CHUNK] = d_g2[base + d - 2 * CHUNK];
    __syncthreads();

    float w[CHUNK];
    #pragma unroll
    for (int r = 0; r < CHUNK; r++)
        w[r] = d_Wh[((size_t)b * NTOK + sp[r]) * D + d];

    float s1a = 0.f, s2a = 0.f;
    #pragma unroll
    for (int r = 0; r < CHUNK; r++) {
        s1a += sg1[r] * w[r];
        s2a += sg2[r] * w[r];
        *(float2*)&d_loc12[((size_t)(base + r) * D + d) * 2] = make_float2(s1a, s2a);
    }
    d_ct1[(b * NCHUNK + c) * D + d] = s1a;
    d_ct2[(b * NCHUNK + c) * D + d] = s2a;
}

// ------- K4: two-phase exclusive scan of 128 chunk totals ---------------------
__global__ void __launch_bounds__(1024) k_coff()
{
    __shared__ float part1[8][D];
    __shared__ float part2[8][D];

    const int b = blockIdx.x;
    const int d = threadIdx.x & 127;
    const int g = threadIdx.x >> 7;

    float v1[16], v2[16];
    #pragma unroll
    for (int r = 0; r < 16; r++) {
        int c = g * 16 + r;
        v1[r] = d_ct1[(b * NCHUNK + c) * D + d];
        v2[r] = d_ct2[(b * NCHUNK + c) * D + d];
    }
    float run1 = 0.f, run2 = 0.f;
    #pragma unroll
    for (int r = 0; r < 16; r++) {
        float t1 = v1[r]; v1[r] = run1; run1 += t1;
        float t2 = v2[r]; v2[r] = run2; run2 += t2;
    }
    part1[g][d] = run1;
    part2[g][d] = run2;
    __syncthreads();

    if (g == 0) {
        float r1 = 0.f, r2 = 0.f;
        #pragma unroll
        for (int gg = 0; gg < 8; gg++) {
            float t1 = part1[gg][d]; part1[gg][d] = r1; r1 += t1;
            float t2 = part2[gg][d]; part2[gg][d] = r2; r2 += t2;
        }
        d_tot1[b * D + d] = r1;
    }
    __syncthreads();

    const float o1 = part1[g][d];
    const float o2 = part2[g][d];
    #pragma unroll
    for (int r = 0; r < 16; r++) {
        int c = g * 16 + r;
        *(float2*)&d_cp12[((size_t)(b * NCHUNK + c) * D + d) * 2] = make_float2(o1 + v1[r], o2 + v2[r]);
    }
}

// ------- K5: wide gather + ELU (interleaved loc/cp reads) ----------------------
__global__ void __launch_bounds__(256) k_out(float* __restrict__ out)
{
    const int gq   = blockIdx.x * 8 + (threadIdx.x >> 5);
    const int lane = threadIdx.x & 31;
    const int b    = gq >> 11;
    const int d4   = lane * 4;

    const int   t  = d_tq[gq];
    const float e1 = d_e1[gq];
    const float e2 = d_e2[gq];

    float4 tot = *(const float4*)&d_tot1[b * D + d4];
    float4 P1 = {0.f, 0.f, 0.f, 0.f};
    float4 P2 = {0.f, 0.f, 0.f, 0.f};

    if (t > 0) {
        int k = t - 1;
        int c = k >> 4;
        size_t kb = ((size_t)(b * NTOK + k) * D + d4) * 2;
        size_t cb = ((size_t)(b * NCHUNK + c) * D + d4) * 2;
        float4 u0 = *(const float4*)&d_loc12[kb];
        float4 u1 = *(const float4*)&d_loc12[kb + 4];
        float4 q0 = *(const float4*)&d_cp12[cb];
        float4 q1 = *(const float4*)&d_cp12[cb + 4];
        P1.x = u0.x + q0.x; P2.x = u0.y + q0.y;
        P1.y = u0.z + q0.z; P2.y = u0.w + q0.w;
        P1.z = u1.x + q1.x; P2.z = u1.y + q1.y;
        P1.w = u1.z + q1.z; P2.w = u1.w + q1.w;
    }

    float4 v;
    v.x = e1 * (tot.x - P1.x) + e2 * P2.x;
    v.y = e1 * (tot.y - P1.y) + e2 * P2.y;
    v.z = e1 * (tot.z - P1.z) + e2 * P2.z;
    v.w = e1 * (tot.w - P1.w) + e2 * P2.w;
    v.x = v.x > 0.f ? v.x : expm1f(v.x);
    v.y = v.y > 0.f ? v.y : expm1f(v.y);
    v.z = v.z > 0.f ? v.z : expm1f(v.z);
    v.w = v.w > 0.f ? v.w : expm1f(v.w);

    *(float4*)&out[(size_t)gq * D + d4] = v;
}

// -----------------------------------------------------------------------------
extern "C" void kernel_launch(void* const* d_in, const int* in_sizes, int n_in,
                              void* d_out, int out_size)
{
    const float* h = (const float*)d_in[0];   // [8,2048,256]
    const float* W = (const float*)d_in[1];   // [256,128]
    const float* a = (const float*)d_in[2];   // [256,1]
    float* out = (float*)d_out;               // [8,2048,128]

    cudaFuncSetAttribute(k_gemm_mma, cudaFuncAttributeMaxDynamicSharedMemorySize, SM_TOT);

    k_wconv<<<FIN * D / 256, 256>>>(W);
    k_gemm_mma<<<(B * NTOK) / 64, 256, SM_TOT>>>(h, a);
    k_sort <<<dim3(2, B), 1024>>>();
    k_gfill<<<dim3(8, B, 2), 256>>>();
    k_scan <<<dim3(NCHUNK, B), 128>>>();
    k_coff <<<B, 1024>>>();
    k_out  <<<(B * NTOK) / 8, 256>>>(out);
}